// round 12
// baseline (speedup 1.0000x reference)
// rev: r12-resubmit-of-16warp-gemm (content identical to r10/r11 modulo this marker)
#include <cuda_runtime.h>
#include <cuda_bf16.h>
#include <math.h>
#include <stdint.h>

// Problem constants
#define LAY 6
#define HH  8
#define DD  512
#define DK  64
#define DFF 2048
#define BB  8
#define SS  1024
#define NN  (BB*SS)          // 8192 rows

// ---------------- scratch (device globals: allocation-free) ----------------
__device__ float g_x[NN*DD];          // fp32 residual stream
__device__ float g_t[NN*DD];          // fp32 pre-LN buffer
__device__ __nv_bfloat16 g_xs[2*NN*DD];
__device__ __nv_bfloat16 g_qs[2*NN*DD];
__device__ __nv_bfloat16 g_ks[2*NN*DD];
__device__ __nv_bfloat16 g_vs[2*NN*DD];
__device__ __nv_bfloat16 g_os[2*NN*DD];
__device__ __nv_bfloat16 g_fs[2*NN*DFF];

// pre-split weights: per 128n x 64k tile: 8192 bf16 hi + 8192 bf16 lo
#define TILE_ELEMS 16384
__device__ __nv_bfloat16 g_wq_s[LAY*4*8*TILE_ELEMS];
__device__ __nv_bfloat16 g_wk_s[LAY*4*8*TILE_ELEMS];
__device__ __nv_bfloat16 g_wv_s[LAY*4*8*TILE_ELEMS];
__device__ __nv_bfloat16 g_wo_s[LAY*4*8*TILE_ELEMS];
__device__ __nv_bfloat16 g_w1_s[LAY*16*8*TILE_ELEMS];
__device__ __nv_bfloat16 g_w2_s[LAY*4*32*TILE_ELEMS];

// ---------------- PTX helpers ----------------
__device__ __forceinline__ uint32_t smem_u32(const void* p) {
    uint32_t a;
    asm("{ .reg .u64 t; cvta.to.shared.u64 t, %1; cvt.u32.u64 %0, t; }" : "=r"(a) : "l"(p));
    return a;
}
#define LDSM4(r, a) \
    asm volatile("ldmatrix.sync.aligned.m8n8.x4.shared.b16 {%0,%1,%2,%3}, [%4];" \
        : "=r"((r)[0]), "=r"((r)[1]), "=r"((r)[2]), "=r"((r)[3]) : "r"(a))
#define LDSM4T(r, a) \
    asm volatile("ldmatrix.sync.aligned.m8n8.x4.trans.shared.b16 {%0,%1,%2,%3}, [%4];" \
        : "=r"((r)[0]), "=r"((r)[1]), "=r"((r)[2]), "=r"((r)[3]) : "r"(a))
#define MMA_BF16(d, a, b0, b1) \
    asm volatile("mma.sync.aligned.m16n8k16.row.col.f32.bf16.bf16.f32 " \
        "{%0,%1,%2,%3}, {%4,%5,%6,%7}, {%8,%9}, {%0,%1,%2,%3};" \
        : "+f"((d)[0]), "+f"((d)[1]), "+f"((d)[2]), "+f"((d)[3]) \
        : "r"((a)[0]), "r"((a)[1]), "r"((a)[2]), "r"((a)[3]), "r"(b0), "r"(b1))
#define CP16(dst, src) \
    asm volatile("cp.async.cg.shared.global [%0], [%1], 16;" :: "r"(dst), "l"(src))
#define CP_COMMIT() asm volatile("cp.async.commit_group;" ::: "memory")
#define CP_WAIT1()  asm volatile("cp.async.wait_group 1;" ::: "memory")

// fast e^x on the FMA pipe (x <= 0 path)
__device__ __forceinline__ float fexp(float x) {
    float t = x * 1.44269504f;
    t = fmaxf(t, -126.0f);
    float i = rintf(t);
    float f = t - i;
    float p =       1.54035304e-4f;
    p = fmaf(p, f, 1.33335581e-3f);
    p = fmaf(p, f, 9.61812910e-3f);
    p = fmaf(p, f, 5.55041086e-2f);
    p = fmaf(p, f, 2.40226507e-1f);
    p = fmaf(p, f, 6.93147182e-1f);
    p = fmaf(p, f, 1.0f);
    return p * __int_as_float(((int)i + 127) << 23);
}

__device__ __forceinline__ void split2(float a, float b, uint32_t& hi, uint32_t& lo) {
    __nv_bfloat162 h = __floats2bfloat162_rn(a, b);
    __nv_bfloat162 l = __floats2bfloat162_rn(a - __bfloat162float(h.x),
                                             b - __bfloat162float(h.y));
    hi = *(uint32_t*)&h;
    lo = *(uint32_t*)&l;
}

// ---------------- weight pre-split: ALL weights in one launch ----------------
__device__ __forceinline__ void split_tile(const float* __restrict__ W,
                                           __nv_bfloat16* __restrict__ out,
                                           int K, int N, int blocked, int tile,
                                           float (*s)[65]) {
    int kt = tile % (K >> 6);
    int rest = tile / (K >> 6);
    int nt = rest % (N >> 7);
    int l = rest / (N >> 7);
    int n0 = nt << 7, k0 = kt << 6;
    int t = threadIdx.x;
#pragma unroll
    for (int r = 0; r < 32; r++) {
        int i = r * 256 + t;
        int k = i >> 7, n = i & 127;
        float x;
        if (blocked) x = W[(((size_t)l * HH + ((n0 + n) >> 6)) * DD + k0 + k) * DK + ((n0 + n) & 63)];
        else         x = W[((size_t)l * K + k0 + k) * N + n0 + n];
        s[n][k] = x;
    }
    __syncthreads();
    uint32_t* oh = (uint32_t*)(out + (size_t)tile * TILE_ELEMS);
    uint32_t* ol = oh + 4096;
#pragma unroll
    for (int r = 0; r < 16; r++) {
        int i = r * 256 + t;
        int n = i >> 5, k = (i & 31) << 1;
        uint32_t hi, lo;
        split2(s[n][k], s[n][k + 1], hi, lo);
        oh[n * 32 + (k >> 1)] = hi;
        ol[n * 32 + (k >> 1)] = lo;
    }
}

__global__ __launch_bounds__(256)
void split_all_kernel(const float* Wq, const float* Wk, const float* Wv,
                      const float* Wo, const float* W1, const float* W2,
                      __nv_bfloat16* oq, __nv_bfloat16* ok, __nv_bfloat16* ov,
                      __nv_bfloat16* oo, __nv_bfloat16* o1, __nv_bfloat16* o2) {
    __shared__ float s[128][65];
    int b = blockIdx.x;
    if      (b < 192)  split_tile(Wq, oq, DD,  DD,  1, b,        s);
    else if (b < 384)  split_tile(Wk, ok, DD,  DD,  1, b - 192,  s);
    else if (b < 576)  split_tile(Wv, ov, DD,  DD,  1, b - 384,  s);
    else if (b < 768)  split_tile(Wo, oo, DD,  DD,  0, b - 576,  s);
    else if (b < 1536) split_tile(W1, o1, DD,  DFF, 0, b - 768,  s);
    else               split_tile(W2, o2, DFF, DD,  0, b - 1536, s);
}

// ---------------- positional encoding (+ split write) ----------------
__global__ void add_pe_kernel(const float* __restrict__ src, float* __restrict__ x,
                              __nv_bfloat16* __restrict__ xh, __nv_bfloat16* __restrict__ xl) {
    int gid = blockIdx.x * 256 + threadIdx.x;
    if (gid >= NN * DD / 2) return;
    int idx = gid * 2;
    int d = idx & (DD - 1);
    int s = (idx >> 9) & (SS - 1);
    int i = d >> 1;
    double div = exp((double)(2 * i) * (-9.210340371976184 / (double)DD));
    double ang = (double)s * div;
    float v0 = src[idx]     + (float)sin(ang);
    float v1 = src[idx + 1] + (float)cos(ang);
    x[idx] = v0; x[idx + 1] = v1;
    uint32_t hi, lo;
    split2(v0, v1, hi, lo);
    ((uint32_t*)xh)[gid] = hi;
    ((uint32_t*)xl)[gid] = lo;
}

// --- HMMA GEMM (bf16x3, 256x128 CTA, 16 warps of 64x32, 3-stage cp.async) ---
// stage (61440 B): A_hi 256x(64+16pad)B @0, A_lo @20480, B_hi @40960, B_lo @51200
#define GS_ALO 20480
#define GS_BHI 40960
#define GS_BLO 10240     /* offset from GS_BHI */
#define GS_STG 61440
#define SMEM_DYN (3*GS_STG)
#define GT 512           /* threads */

// AMODE 0: A rowmajor.  AMODE 1: A bhsk gather.
// OMODE 0: fp32 rowmajor.  OMODE 1: split bhsk.  OMODE 2: split rowmajor.
template<int AMODE, int OMODE, bool RELU>
__global__ __launch_bounds__(GT, 1)
void hmma_gemm(const __nv_bfloat16* __restrict__ Ah, const __nv_bfloat16* __restrict__ Al,
               const __nv_bfloat16* __restrict__ Bt,
               const float* __restrict__ bias, float* __restrict__ Cf,
               __nv_bfloat16* __restrict__ Chi, __nv_bfloat16* __restrict__ Clo,
               int M, int N, int K, float scale) {
    extern __shared__ char smbuf[];
    uint32_t sb = smem_u32(smbuf);
    const int t = threadIdx.x, lane = t & 31, wid = t >> 5;
    const int wm = wid & 3, wn = wid >> 2;          // 4x4 warp grid
    const int bm = blockIdx.y * 256, bn = blockIdx.x * 128;
    const int nk = K >> 5;
    const int ktile_n = K >> 6;

    float acc[4][4][4];                              // mt x n8-block x frag
#pragma unroll
    for (int a = 0; a < 4; a++)
#pragma unroll
        for (int b = 0; b < 4; b++)
#pragma unroll
            for (int c = 0; c < 4; c++) acc[a][b][c] = 0.f;

    auto ISSUE = [&](int kt) {
        uint32_t stg = sb + (kt % 3) * GS_STG;
        // A: 2048 16B chunks (hi/lo x 256 rows x 4)
#pragma unroll
        for (int r = 0; r < 4; r++) {
            int i = r * GT + t;
            int comp = i >> 10, j = i & 1023;
            int row = j >> 2, ch = j & 3;
            const char* base = (const char*)(comp ? Al : Ah);
            const char* src;
            if (AMODE == 0) {
                src = base + (((size_t)(bm + row) * K + kt * 32 + ch * 8) << 1);
            } else {
                int kk = kt * 32 + ch * 8;
                int mm = bm + row;
                src = base + (((size_t)(((mm >> 10) << 3) + (kk >> 6))) << 17)
                           + ((mm & 1023) << 7) + ((kk & 63) << 1);
            }
            CP16(stg + comp * GS_ALO + row * 80 + ch * 16, src);
        }
        // B: 1024 16B chunks from pre-swizzled tile
        const char* tb = (const char*)(Bt + ((size_t)blockIdx.x * ktile_n + (kt >> 1)) * TILE_ELEMS);
        int half = kt & 1;
#pragma unroll
        for (int r = 0; r < 2; r++) {
            int i = r * GT + t;
            int comp = i >> 9, j = i & 511;
            int row = j >> 2, ch = j & 3;
            CP16(stg + GS_BHI + comp * GS_BLO + row * 80 + ch * 16,
                 tb + comp * 16384 + row * 128 + half * 64 + ch * 16);
        }
    };

    auto COMPUTE = [&](int buf) {
        uint32_t stg = sb + buf * GS_STG;
#pragma unroll
        for (int kk = 0; kk < 2; kk++) {
            int acol = (kk * 16 + (lane >> 4) * 8) * 2;
            uint32_t af[4][2][4];
#pragma unroll
            for (int mt = 0; mt < 4; mt++) {
                uint32_t aaddr = stg + (wm * 64 + mt * 16 + (lane & 15)) * 80 + acol;
                LDSM4(af[mt][0], aaddr);
                LDSM4(af[mt][1], aaddr + GS_ALO);
            }
#pragma unroll
            for (int nt2 = 0; nt2 < 2; nt2++) {
                uint32_t baddr = stg + GS_BHI + (wn * 32 + nt2 * 16 + (lane & 15)) * 80 + acol;
                uint32_t bh[4], bl[4];
                LDSM4(bh, baddr);
                LDSM4(bl, baddr + GS_BLO);
#pragma unroll
                for (int mt = 0; mt < 4; mt++) {
                    MMA_BF16(acc[mt][nt2 * 2],     af[mt][0], bh[0], bh[2]);
                    MMA_BF16(acc[mt][nt2 * 2],     af[mt][0], bl[0], bl[2]);
                    MMA_BF16(acc[mt][nt2 * 2],     af[mt][1], bh[0], bh[2]);
                    MMA_BF16(acc[mt][nt2 * 2 + 1], af[mt][0], bh[1], bh[3]);
                    MMA_BF16(acc[mt][nt2 * 2 + 1], af[mt][0], bl[1], bl[3]);
                    MMA_BF16(acc[mt][nt2 * 2 + 1], af[mt][1], bh[1], bh[3]);
                }
            }
        }
    };

    ISSUE(0); CP_COMMIT();
    ISSUE(1); CP_COMMIT();
    for (int kt = 0; kt < nk; kt++) {
        CP_WAIT1();
        __syncthreads();
        if (kt + 2 < nk) ISSUE(kt + 2);
        CP_COMMIT();
        COMPUTE(kt % 3);
    }

    const int mrow = lane >> 2, ncol = (lane & 3) * 2;
#pragma unroll
    for (int mt = 0; mt < 4; mt++) {
#pragma unroll
        for (int nb = 0; nb < 4; nb++) {
            int c = bn + wn * 32 + nb * 8 + ncol;
            float2 bi = *(const float2*)(bias + c);
#pragma unroll
            for (int h = 0; h < 2; h++) {
                int m = bm + wm * 64 + mt * 16 + mrow + h * 8;
                float2 v;
                v.x = (acc[mt][nb][h * 2 + 0] + bi.x) * scale;
                v.y = (acc[mt][nb][h * 2 + 1] + bi.y) * scale;
                if (RELU) { v.x = fmaxf(v.x, 0.f); v.y = fmaxf(v.y, 0.f); }
                if (OMODE == 0) {
                    *(float2*)(Cf + (size_t)m * N + c) = v;
                } else if (OMODE == 1) {
                    size_t idx = (((size_t)(((m >> 10) << 3) + (c >> 6))) << 16)
                               + ((m & 1023) << 6) + (c & 63);
                    uint32_t hi, lo;
                    split2(v.x, v.y, hi, lo);
                    ((uint32_t*)Chi)[idx >> 1] = hi;
                    ((uint32_t*)Clo)[idx >> 1] = lo;
                } else {
                    size_t idx = (size_t)m * N + c;
                    uint32_t hi, lo;
                    split2(v.x, v.y, hi, lo);
                    ((uint32_t*)Chi)[idx >> 1] = hi;
                    ((uint32_t*)Clo)[idx >> 1] = lo;
                }
            }
        }
    }
}

// ---------------- HMMA flash attention (pre-split inputs, cp.async KV) -------
#define AQ_LO  18432
#define KVB    36864
#define KV_STG 36864
#define KV_KL  9216
#define KV_VH  18432
#define ATT_SMEM (36864 + 3*36864)

__global__ __launch_bounds__(256)
void attn_hmma(const __nv_bfloat16* __restrict__ Qh, const __nv_bfloat16* __restrict__ Ql,
               const __nv_bfloat16* __restrict__ Kh, const __nv_bfloat16* __restrict__ Kl,
               const __nv_bfloat16* __restrict__ Vh, const __nv_bfloat16* __restrict__ Vl,
               __nv_bfloat16* __restrict__ Oh, __nv_bfloat16* __restrict__ Ol) {
    extern __shared__ char smbuf[];
    uint32_t sb = smem_u32(smbuf);
    const int t = threadIdx.x, lane = t & 31, w = t >> 5;
    const int bh = blockIdx.x;
    const int qbase = blockIdx.y * 128;

    auto ISSUEKV = [&](int c) {
        uint32_t stg = sb + KVB + (c % 3) * KV_STG;
        int kc = c * 64;
#pragma unroll
        for (int r = 0; r < 8; r++) {
            int i = r * 256 + t;
            int ts = i >> 10;
            int j = i & 1023;
            int comp = j >> 9;
            int jj = j & 511;
            int row = jj >> 3, ch = jj & 7;
            const char* base = ts ? (const char*)(comp ? Vl : Vh)
                                  : (const char*)(comp ? Kl : Kh);
            const char* src = base + (((size_t)(bh * SS + kc + row) * DK + ch * 8) << 1);
            CP16(stg + ts * 18432 + comp * 9216 + row * 144 + ch * 16, src);
        }
    };

    ISSUEKV(0); CP_COMMIT();
    ISSUEKV(1); CP_COMMIT();

#pragma unroll
    for (int r = 0; r < 8; r++) {
        int i = r * 256 + t;
        int comp = i >> 10;
        int j = i & 1023;
        int row = j >> 3, ch = j & 7;
        const char* src = (comp ? (const char*)Ql : (const char*)Qh)
                        + (((size_t)(bh * SS + qbase + row) * DK + ch * 8) << 1);
        *(uint4*)(smbuf + comp * AQ_LO + row * 144 + ch * 16) = *(const uint4*)src;
    }
    __syncthreads();

    uint32_t qh[4][4], ql[4][4];
#pragma unroll
    for (int kb = 0; kb < 4; kb++) {
        uint32_t addr = sb + (w * 16 + (lane & 15)) * 144 + (kb * 16 + (lane >> 4) * 8) * 2;
        LDSM4(qh[kb], addr);
        LDSM4(ql[kb], addr + AQ_LO);
    }

    float o[8][4];
#pragma unroll
    for (int i = 0; i < 8; i++)
#pragma unroll
        for (int j = 0; j < 4; j++) o[i][j] = 0.f;
    float m0 = -1.0e30f, m1 = -1.0e30f, l0 = 0.f, l1 = 0.f;

    for (int c = 0; c < SS / 64; c++) {
        CP_WAIT1();
        __syncthreads();
        if (c + 2 < SS / 64) ISSUEKV(c + 2);
        CP_COMMIT();
        uint32_t stg = sb + KVB + (c % 3) * KV_STG;

        float s[8][4];
#pragma unroll
        for (int i = 0; i < 8; i++)
#pragma unroll
            for (int j = 0; j < 4; j++) s[i][j] = 0.f;
#pragma unroll
        for (int kvb = 0; kvb < 4; kvb++) {
#pragma unroll
            for (int kb = 0; kb < 4; kb++) {
                uint32_t addr = stg + (kvb * 16 + (lane & 15)) * 144 + (kb * 16 + (lane >> 4) * 8) * 2;
                uint32_t kfh[4], kfl[4];
                LDSM4(kfh, addr);
                LDSM4(kfl, addr + KV_KL);
                MMA_BF16(s[kvb * 2],     qh[kb], kfh[0], kfh[2]);
                MMA_BF16(s[kvb * 2],     qh[kb], kfl[0], kfl[2]);
                MMA_BF16(s[kvb * 2],     ql[kb], kfh[0], kfh[2]);
                MMA_BF16(s[kvb * 2 + 1], qh[kb], kfh[1], kfh[3]);
                MMA_BF16(s[kvb * 2 + 1], qh[kb], kfl[1], kfl[3]);
                MMA_BF16(s[kvb * 2 + 1], ql[kb], kfh[1], kfh[3]);
            }
        }

        float cm0 = -1.0e30f, cm1 = -1.0e30f;
#pragma unroll
        for (int nb = 0; nb < 8; nb++) {
            cm0 = fmaxf(cm0, fmaxf(s[nb][0], s[nb][1]));
            cm1 = fmaxf(cm1, fmaxf(s[nb][2], s[nb][3]));
        }
        cm0 = fmaxf(cm0, __shfl_xor_sync(0xffffffffu, cm0, 1));
        cm0 = fmaxf(cm0, __shfl_xor_sync(0xffffffffu, cm0, 2));
        cm1 = fmaxf(cm1, __shfl_xor_sync(0xffffffffu, cm1, 1));
        cm1 = fmaxf(cm1, __shfl_xor_sync(0xffffffffu, cm1, 2));
        float m0n = fmaxf(m0, cm0), m1n = fmaxf(m1, cm1);
        float c0 = fexp(m0 - m0n), c1 = fexp(m1 - m1n);
#pragma unroll
        for (int nb = 0; nb < 8; nb++) {
            o[nb][0] *= c0; o[nb][1] *= c0;
            o[nb][2] *= c1; o[nb][3] *= c1;
        }
        float ls0 = 0.f, ls1 = 0.f;
#pragma unroll
        for (int nb = 0; nb < 8; nb++) {
            s[nb][0] = fexp(s[nb][0] - m0n);
            s[nb][1] = fexp(s[nb][1] - m0n);
            s[nb][2] = fexp(s[nb][2] - m1n);
            s[nb][3] = fexp(s[nb][3] - m1n);
            ls0 += s[nb][0] + s[nb][1];
            ls1 += s[nb][2] + s[nb][3];
        }
        ls0 += __shfl_xor_sync(0xffffffffu, ls0, 1);
        ls0 += __shfl_xor_sync(0xffffffffu, ls0, 2);
        ls1 += __shfl_xor_sync(0xffffffffu, ls1, 1);
        ls1 += __shfl_xor_sync(0xffffffffu, ls1, 2);
        l0 = l0 * c0 + ls0;
        l1 = l1 * c1 + ls1;
        m0 = m0n; m1 = m1n;

#pragma unroll
        for (int kb = 0; kb < 4; kb++) {
            uint32_t ph[4], pl[4];
            split2(s[2 * kb][0],     s[2 * kb][1],     ph[0], pl[0]);
            split2(s[2 * kb][2],     s[2 * kb][3],     ph[1], pl[1]);
            split2(s[2 * kb + 1][0], s[2 * kb + 1][1], ph[2], pl[2]);
            split2(s[2 * kb + 1][2], s[2 * kb + 1][3], ph[3], pl[3]);
#pragma unroll
            for (int db = 0; db < 4; db++) {
                uint32_t addr = stg + KV_VH + (kb * 16 + (lane & 15)) * 144 + (db * 16 + (lane >> 4) * 8) * 2;
                uint32_t vfh[4], vfl[4];
                LDSM4T(vfh, addr);
                LDSM4T(vfl, addr + KV_KL);
                MMA_BF16(o[db * 2],     ph, vfh[0], vfh[1]);
                MMA_BF16(o[db * 2],     ph, vfl[0], vfl[1]);
                MMA_BF16(o[db * 2],     pl, vfh[0], vfh[1]);
                MMA_BF16(o[db * 2 + 1], ph, vfh[2], vfh[3]);
                MMA_BF16(o[db * 2 + 1], ph, vfl[2], vfl[3]);
                MMA_BF16(o[db * 2 + 1], pl, vfh[2], vfh[3]);
            }
        }
    }

    float inv0 = 1.f / l0, inv1 = 1.f / l1;
    int r0 = qbase + w * 16 + (lane >> 2);
    int c0c = (lane & 3) * 2;
#pragma unroll
    for (int db = 0; db < 8; db++) {
        int c = db * 8 + c0c;
        uint32_t hi, lo;
        size_t idx0 = ((size_t)bh * SS + r0) * DK + c;
        split2(o[db][0] * inv0, o[db][1] * inv0, hi, lo);
        ((uint32_t*)Oh)[idx0 >> 1] = hi;
        ((uint32_t*)Ol)[idx0 >> 1] = lo;
        size_t idx1 = ((size_t)bh * SS + r0 + 8) * DK + c;
        split2(o[db][2] * inv1, o[db][3] * inv1, hi, lo);
        ((uint32_t*)Oh)[idx1 >> 1] = hi;
        ((uint32_t*)Ol)[idx1 >> 1] = lo;
    }
}

// ---------------- LayerNorm (+ optional residual add, + optional split out) --
template<bool ADD, bool SPLIT>
__global__ __launch_bounds__(128)
void ln_kernel(const float* __restrict__ src, const float* __restrict__ gamma,
               const float* __restrict__ beta, float* __restrict__ xio,
               __nv_bfloat16* __restrict__ xh, __nv_bfloat16* __restrict__ xl, float eps) {
    int row = blockIdx.x;
    int t = threadIdx.x;
    int lane = t & 31, wid = t >> 5;
    const float4* sp = (const float4*)(src + (size_t)row * DD);
    float4 v = sp[t];

    __shared__ float red[4];
    __shared__ float bsum, bvar;

    float s = (v.x + v.y) + (v.z + v.w);
#pragma unroll
    for (int o = 16; o > 0; o >>= 1) s += __shfl_xor_sync(0xffffffffu, s, o);
    if (lane == 0) red[wid] = s;
    __syncthreads();
    if (t == 0) bsum = (red[0] + red[1]) + (red[2] + red[3]);
    __syncthreads();
    float mu = bsum * (1.f / DD);

    float dx = v.x - mu, dy = v.y - mu, dz = v.z - mu, dw = v.w - mu;
    float s2 = (dx * dx + dy * dy) + (dz * dz + dw * dw);
#pragma unroll
    for (int o = 16; o > 0; o >>= 1) s2 += __shfl_xor_sync(0xffffffffu, s2, o);
    if (lane == 0) red[wid] = s2;
    __syncthreads();
    if (t == 0) bvar = (red[0] + red[1]) + (red[2] + red[3]);
    __syncthreads();
    float rstd = rsqrtf(bvar * (1.f / DD) + eps);

    int c = t * 4;
    float4 g = *(const float4*)(gamma + c);
    float4 b = *(const float4*)(beta + c);
    float4 o4;
    o4.x = dx * rstd * g.x + b.x;
    o4.y = dy * rstd * g.y + b.y;
    o4.z = dz * rstd * g.z + b.z;
    o4.w = dw * rstd * g.w + b.w;
    float4* xp = (float4*)(xio + (size_t)row * DD);
    if (ADD) {
        float4 xo = xp[t];
        o4.x += xo.x; o4.y += xo.y; o4.z += xo.z; o4.w += xo.w;
    }
    xp[t] = o4;
    if (SPLIT) {
        size_t pidx = ((size_t)row * DD + c) >> 1;
        uint32_t hi, lo;
        split2(o4.x, o4.y, hi, lo);
        ((uint32_t*)xh)[pidx] = hi; ((uint32_t*)xl)[pidx] = lo;
        split2(o4.z, o4.w, hi, lo);
        ((uint32_t*)xh)[pidx + 1] = hi; ((uint32_t*)xl)[pidx + 1] = lo;
    }
}

// ---------------- driver ----------------
extern "C" void kernel_launch(void* const* d_in, const int* in_sizes, int n_in,
                              void* d_out, int out_size) {
    const float* src  = (const float*)d_in[0];
    const float* Wq   = (const float*)d_in[1];
    const float* bq   = (const float*)d_in[2];
    const float* Wk   = (const float*)d_in[3];
    const float* bk   = (const float*)d_in[4];
    const float* Wv   = (const float*)d_in[5];
    const float* bv   = (const float*)d_in[6];
    const float* Wo   = (const float*)d_in[7];
    const float* bo   = (const float*)d_in[8];
    const float* ln1g = (const float*)d_in[9];
    const float* ln1b = (const float*)d_in[10];
    const float* W1   = (const float*)d_in[11];
    const float* b1   = (const float*)d_in[12];
    const float* W2   = (const float*)d_in[13];
    const float* b2   = (const float*)d_in[14];
    const float* ln2g = (const float*)d_in[15];
    const float* ln2b = (const float*)d_in[16];
    const float* lnfg = (const float*)d_in[17];
    const float* lnfb = (const float*)d_in[18];
    float* out = (float*)d_out;

    float *px, *pt;
    __nv_bfloat16 *xs, *qs, *ks, *vs, *os, *fs;
    __nv_bfloat16 *wqs, *wks, *wvs, *wos, *w1s, *w2s;
    cudaGetSymbolAddress((void**)&px, g_x);
    cudaGetSymbolAddress((void**)&pt, g_t);
    cudaGetSymbolAddress((void**)&xs, g_xs);
    cudaGetSymbolAddress((void**)&qs, g_qs);
    cudaGetSymbolAddress((void**)&ks, g_ks);
    cudaGetSymbolAddress((void**)&vs, g_vs);
    cudaGetSymbolAddress((void**)&os, g_os);
    cudaGetSymbolAddress((void**)&fs, g_fs);
    cudaGetSymbolAddress((void**)&wqs, g_wq_s);
    cudaGetSymbolAddress((void**)&wks, g_wk_s);
    cudaGetSymbolAddress((void**)&wvs, g_wv_s);
    cudaGetSymbolAddress((void**)&wos, g_wo_s);
    cudaGetSymbolAddress((void**)&w1s, g_w1_s);
    cudaGetSymbolAddress((void**)&w2s, g_w2_s);

    __nv_bfloat16 *xh = xs, *xl = xs + (size_t)NN * DD;
    __nv_bfloat16 *qh = qs, *ql = qs + (size_t)NN * DD;
    __nv_bfloat16 *kh = ks, *kl = ks + (size_t)NN * DD;
    __nv_bfloat16 *vh = vs, *vl = vs + (size_t)NN * DD;
    __nv_bfloat16 *oh = os, *ol = os + (size_t)NN * DD;
    __nv_bfloat16 *fh = fs, *fl = fs + (size_t)NN * DFF;

    cudaFuncSetAttribute(hmma_gemm<0,1,false>, cudaFuncAttributeMaxDynamicSharedMemorySize, SMEM_DYN);
    cudaFuncSetAttribute(hmma_gemm<1,0,false>, cudaFuncAttributeMaxDynamicSharedMemorySize, SMEM_DYN);
    cudaFuncSetAttribute(hmma_gemm<0,2,true >, cudaFuncAttributeMaxDynamicSharedMemorySize, SMEM_DYN);
    cudaFuncSetAttribute(hmma_gemm<0,0,false>, cudaFuncAttributeMaxDynamicSharedMemorySize, SMEM_DYN);
    cudaFuncSetAttribute(attn_hmma, cudaFuncAttributeMaxDynamicSharedMemorySize, ATT_SMEM);

    split_all_kernel<<<2304, 256>>>(Wq, Wk, Wv, Wo, W1, W2, wqs, wks, wvs, wos, w1s, w2s);
    add_pe_kernel<<<(NN * DD / 2 + 255) / 256, 256>>>(src, px, xh, xl);

    dim3 gProj(4, 32);    // N=512, M tiles of 256
    dim3 gFfn1(16, 32);   // N=2048
    dim3 gAttn(BB * HH, SS / 128);

    for (int l = 0; l < LAY; l++) {
        size_t ws_proj = (size_t)l * 4 * 8 * TILE_ELEMS;
        size_t ws_w1   = (size_t)l * 16 * 8 * TILE_ELEMS;
        size_t ws_w2   = (size_t)l * 4 * 32 * TILE_ELEMS;

        hmma_gemm<0,1,false><<<gProj, GT, SMEM_DYN>>>(xh, xl, wqs + ws_proj, bq + l * HH * DK,
                                                      nullptr, qh, ql, NN, DD, DD, 0.125f);
        hmma_gemm<0,1,false><<<gProj, GT, SMEM_DYN>>>(xh, xl, wks + ws_proj, bk + l * HH * DK,
                                                      nullptr, kh, kl, NN, DD, DD, 1.0f);
        hmma_gemm<0,1,false><<<gProj, GT, SMEM_DYN>>>(xh, xl, wvs + ws_proj, bv + l * HH * DK,
                                                      nullptr, vh, vl, NN, DD, DD, 1.0f);

        attn_hmma<<<gAttn, 256, ATT_SMEM>>>(qh, ql, kh, kl, vh, vl, oh, ol);

        hmma_gemm<1,0,false><<<gProj, GT, SMEM_DYN>>>(oh, ol, wos + ws_proj, bo + l * DD,
                                                      pt, nullptr, nullptr, NN, DD, DD, 1.0f);
        ln_kernel<true,true><<<NN, 128>>>(pt, ln1g + l * DD, ln1b + l * DD, px, xh, xl, 1e-5f);

        hmma_gemm<0,2,true ><<<gFfn1, GT, SMEM_DYN>>>(xh, xl, w1s + ws_w1, b1 + l * DFF,
                                                      nullptr, fh, fl, NN, DFF, DD, 1.0f);
        hmma_gemm<0,0,false><<<gProj, GT, SMEM_DYN>>>(fh, fl, w2s + ws_w2, b2 + l * DD,
                                                      pt, nullptr, nullptr, NN, DD, DFF, 1.0f);
        ln_kernel<true,true><<<NN, 128>>>(pt, ln2g + l * DD, ln2b + l * DD, px, xh, xl, 1e-5f);
    }

    ln_kernel<false,false><<<NN, 128>>>(px, lnfg, lnfb, out, nullptr, nullptr, 1e-6f);
}

// round 14
// speedup vs baseline: 1.1952x; 1.1952x over previous
// rev: r14-resubmit of fp16 2-term FFN (identical to r13 modulo this marker)
#include <cuda_runtime.h>
#include <cuda_bf16.h>
#include <cuda_fp16.h>
#include <math.h>
#include <stdint.h>

#define LAY 6
#define HH  8
#define DD  512
#define DK  64
#define DFF 2048
#define BB  8
#define SS  1024
#define NN  (BB*SS)

// ---------------- scratch ----------------
__device__ float g_x[NN*DD];
__device__ float g_t[NN*DD];
__device__ __nv_bfloat16 g_xs[2*NN*DD];
__device__ __nv_bfloat16 g_qs[2*NN*DD];
__device__ __nv_bfloat16 g_ks[2*NN*DD];
__device__ __nv_bfloat16 g_vs[2*NN*DD];
__device__ __nv_bfloat16 g_os[2*NN*DD];
__device__ __half        g_xf[NN*DD];       // fp16 single x (FFN1 A)
__device__ __half        g_ff[NN*DFF];      // fp16 single ffn hidden (FFN2 A)

#define TILE_ELEMS 16384
__device__ __nv_bfloat16 g_wq_s[LAY*4*8*TILE_ELEMS];
__device__ __nv_bfloat16 g_wk_s[LAY*4*8*TILE_ELEMS];
__device__ __nv_bfloat16 g_wv_s[LAY*4*8*TILE_ELEMS];
__device__ __nv_bfloat16 g_wo_s[LAY*4*8*TILE_ELEMS];
__device__ __half        g_w1h[LAY*16*8*TILE_ELEMS];   // fp16 hi/lo tiles
__device__ __half        g_w2h[LAY*4*32*TILE_ELEMS];

// ---------------- PTX helpers ----------------
__device__ __forceinline__ uint32_t smem_u32(const void* p) {
    uint32_t a;
    asm("{ .reg .u64 t; cvta.to.shared.u64 t, %1; cvt.u32.u64 %0, t; }" : "=r"(a) : "l"(p));
    return a;
}
#define LDSM4(r, a) \
    asm volatile("ldmatrix.sync.aligned.m8n8.x4.shared.b16 {%0,%1,%2,%3}, [%4];" \
        : "=r"((r)[0]), "=r"((r)[1]), "=r"((r)[2]), "=r"((r)[3]) : "r"(a))
#define LDSM4T(r, a) \
    asm volatile("ldmatrix.sync.aligned.m8n8.x4.trans.shared.b16 {%0,%1,%2,%3}, [%4];" \
        : "=r"((r)[0]), "=r"((r)[1]), "=r"((r)[2]), "=r"((r)[3]) : "r"(a))
#define MMA_BF16(d, a, b0, b1) \
    asm volatile("mma.sync.aligned.m16n8k16.row.col.f32.bf16.bf16.f32 " \
        "{%0,%1,%2,%3}, {%4,%5,%6,%7}, {%8,%9}, {%0,%1,%2,%3};" \
        : "+f"((d)[0]), "+f"((d)[1]), "+f"((d)[2]), "+f"((d)[3]) \
        : "r"((a)[0]), "r"((a)[1]), "r"((a)[2]), "r"((a)[3]), "r"(b0), "r"(b1))
#define MMA_F16(d, a, b0, b1) \
    asm volatile("mma.sync.aligned.m16n8k16.row.col.f32.f16.f16.f32 " \
        "{%0,%1,%2,%3}, {%4,%5,%6,%7}, {%8,%9}, {%0,%1,%2,%3};" \
        : "+f"((d)[0]), "+f"((d)[1]), "+f"((d)[2]), "+f"((d)[3]) \
        : "r"((a)[0]), "r"((a)[1]), "r"((a)[2]), "r"((a)[3]), "r"(b0), "r"(b1))
#define CP16(dst, src) \
    asm volatile("cp.async.cg.shared.global [%0], [%1], 16;" :: "r"(dst), "l"(src))
#define CP_COMMIT() asm volatile("cp.async.commit_group;" ::: "memory")
#define CP_WAIT1()  asm volatile("cp.async.wait_group 1;" ::: "memory")

__device__ __forceinline__ float fexp(float x) {
    float t = x * 1.44269504f;
    t = fmaxf(t, -126.0f);
    float i = rintf(t);
    float f = t - i;
    float p =       1.54035304e-4f;
    p = fmaf(p, f, 1.33335581e-3f);
    p = fmaf(p, f, 9.61812910e-3f);
    p = fmaf(p, f, 5.55041086e-2f);
    p = fmaf(p, f, 2.40226507e-1f);
    p = fmaf(p, f, 6.93147182e-1f);
    p = fmaf(p, f, 1.0f);
    return p * __int_as_float(((int)i + 127) << 23);
}

__device__ __forceinline__ void split2(float a, float b, uint32_t& hi, uint32_t& lo) {
    __nv_bfloat162 h = __floats2bfloat162_rn(a, b);
    __nv_bfloat162 l = __floats2bfloat162_rn(a - __bfloat162float(h.x),
                                             b - __bfloat162float(h.y));
    hi = *(uint32_t*)&h;
    lo = *(uint32_t*)&l;
}
__device__ __forceinline__ void split2h(float a, float b, uint32_t& hi, uint32_t& lo) {
    __half2 h = __floats2half2_rn(a, b);
    __half2 l = __floats2half2_rn(a - __half2float(__low2half(h)),
                                  b - __half2float(__high2half(h)));
    hi = *(uint32_t*)&h;
    lo = *(uint32_t*)&l;
}
__device__ __forceinline__ uint32_t h2pack(float a, float b) {
    __half2 h = __floats2half2_rn(a, b);
    return *(uint32_t*)&h;
}

// ---------------- weight pre-split (bf16 for proj, fp16 for FFN) -------------
__device__ __forceinline__ void split_tile(const float* __restrict__ W,
                                           __nv_bfloat16* __restrict__ out,
                                           int K, int N, int blocked, int tile,
                                           float (*s)[65]) {
    int kt = tile % (K >> 6);
    int rest = tile / (K >> 6);
    int nt = rest % (N >> 7);
    int l = rest / (N >> 7);
    int n0 = nt << 7, k0 = kt << 6;
    int t = threadIdx.x;
#pragma unroll
    for (int r = 0; r < 32; r++) {
        int i = r * 256 + t;
        int k = i >> 7, n = i & 127;
        float x;
        if (blocked) x = W[(((size_t)l * HH + ((n0 + n) >> 6)) * DD + k0 + k) * DK + ((n0 + n) & 63)];
        else         x = W[((size_t)l * K + k0 + k) * N + n0 + n];
        s[n][k] = x;
    }
    __syncthreads();
    uint32_t* oh = (uint32_t*)(out + (size_t)tile * TILE_ELEMS);
    uint32_t* ol = oh + 4096;
#pragma unroll
    for (int r = 0; r < 16; r++) {
        int i = r * 256 + t;
        int n = i >> 5, k = (i & 31) << 1;
        uint32_t hi, lo;
        split2(s[n][k], s[n][k + 1], hi, lo);
        oh[n * 32 + (k >> 1)] = hi;
        ol[n * 32 + (k >> 1)] = lo;
    }
}
__device__ __forceinline__ void split_tile_h(const float* __restrict__ W,
                                             __half* __restrict__ out,
                                             int K, int N, int tile,
                                             float (*s)[65]) {
    int kt = tile % (K >> 6);
    int rest = tile / (K >> 6);
    int nt = rest % (N >> 7);
    int l = rest / (N >> 7);
    int n0 = nt << 7, k0 = kt << 6;
    int t = threadIdx.x;
#pragma unroll
    for (int r = 0; r < 32; r++) {
        int i = r * 256 + t;
        int k = i >> 7, n = i & 127;
        s[n][k] = W[((size_t)l * K + k0 + k) * N + n0 + n];
    }
    __syncthreads();
    uint32_t* oh = (uint32_t*)(out + (size_t)tile * TILE_ELEMS);
    uint32_t* ol = oh + 4096;
#pragma unroll
    for (int r = 0; r < 16; r++) {
        int i = r * 256 + t;
        int n = i >> 5, k = (i & 31) << 1;
        uint32_t hi, lo;
        split2h(s[n][k], s[n][k + 1], hi, lo);
        oh[n * 32 + (k >> 1)] = hi;
        ol[n * 32 + (k >> 1)] = lo;
    }
}

__global__ __launch_bounds__(256)
void split_all_kernel(const float* Wq, const float* Wk, const float* Wv,
                      const float* Wo, const float* W1, const float* W2,
                      __nv_bfloat16* oq, __nv_bfloat16* ok, __nv_bfloat16* ov,
                      __nv_bfloat16* oo, __half* o1, __half* o2) {
    __shared__ float s[128][65];
    int b = blockIdx.x;
    if      (b < 192)  split_tile(Wq, oq, DD,  DD,  1, b,        s);
    else if (b < 384)  split_tile(Wk, ok, DD,  DD,  1, b - 192,  s);
    else if (b < 576)  split_tile(Wv, ov, DD,  DD,  1, b - 384,  s);
    else if (b < 768)  split_tile(Wo, oo, DD,  DD,  0, b - 576,  s);
    else if (b < 1536) split_tile_h(W1, o1, DD,  DFF, b - 768,  s);
    else               split_tile_h(W2, o2, DFF, DD,  b - 1536, s);
}

// ---------------- positional encoding ----------------
__global__ void add_pe_kernel(const float* __restrict__ src, float* __restrict__ x,
                              __nv_bfloat16* __restrict__ xh, __nv_bfloat16* __restrict__ xl,
                              __half* __restrict__ xf) {
    int gid = blockIdx.x * 256 + threadIdx.x;
    if (gid >= NN * DD / 2) return;
    int idx = gid * 2;
    int d = idx & (DD - 1);
    int s = (idx >> 9) & (SS - 1);
    int i = d >> 1;
    double div = exp((double)(2 * i) * (-9.210340371976184 / (double)DD));
    double ang = (double)s * div;
    float v0 = src[idx]     + (float)sin(ang);
    float v1 = src[idx + 1] + (float)cos(ang);
    x[idx] = v0; x[idx + 1] = v1;
    uint32_t hi, lo;
    split2(v0, v1, hi, lo);
    ((uint32_t*)xh)[gid] = hi;
    ((uint32_t*)xl)[gid] = lo;
    ((uint32_t*)xf)[gid] = h2pack(v0, v1);
}

// --- bf16x3 HMMA GEMM (256x128 CTA, 16 warps of 64x32, 3-stage cp.async) -----
#define GS_ALO 20480
#define GS_BHI 40960
#define GS_BLO 10240
#define GS_STG 61440
#define SMEM_DYN (3*GS_STG)
#define GT 512

// AMODE 0: A rowmajor.  AMODE 1: A bhsk gather.
// OMODE 0: fp32 rowmajor.  OMODE 1: split bhsk.
template<int AMODE, int OMODE>
__global__ __launch_bounds__(GT, 1)
void hmma_gemm(const __nv_bfloat16* __restrict__ Ah, const __nv_bfloat16* __restrict__ Al,
               const __nv_bfloat16* __restrict__ Bt,
               const float* __restrict__ bias, float* __restrict__ Cf,
               __nv_bfloat16* __restrict__ Chi, __nv_bfloat16* __restrict__ Clo,
               int M, int N, int K, float scale) {
    extern __shared__ char smbuf[];
    uint32_t sb = smem_u32(smbuf);
    const int t = threadIdx.x, lane = t & 31, wid = t >> 5;
    const int wm = wid & 3, wn = wid >> 2;
    const int bm = blockIdx.y * 256, bn = blockIdx.x * 128;
    const int nk = K >> 5;
    const int ktile_n = K >> 6;

    float acc[4][4][4];
#pragma unroll
    for (int a = 0; a < 4; a++)
#pragma unroll
        for (int b = 0; b < 4; b++)
#pragma unroll
            for (int c = 0; c < 4; c++) acc[a][b][c] = 0.f;

    auto ISSUE = [&](int kt) {
        uint32_t stg = sb + (kt % 3) * GS_STG;
#pragma unroll
        for (int r = 0; r < 4; r++) {
            int i = r * GT + t;
            int comp = i >> 10, j = i & 1023;
            int row = j >> 2, ch = j & 3;
            const char* base = (const char*)(comp ? Al : Ah);
            const char* src;
            if (AMODE == 0) {
                src = base + (((size_t)(bm + row) * K + kt * 32 + ch * 8) << 1);
            } else {
                int kk = kt * 32 + ch * 8;
                int mm = bm + row;
                src = base + (((size_t)(((mm >> 10) << 3) + (kk >> 6))) << 17)
                           + ((mm & 1023) << 7) + ((kk & 63) << 1);
            }
            CP16(stg + comp * GS_ALO + row * 80 + ch * 16, src);
        }
        const char* tb = (const char*)(Bt + ((size_t)blockIdx.x * ktile_n + (kt >> 1)) * TILE_ELEMS);
        int half = kt & 1;
#pragma unroll
        for (int r = 0; r < 2; r++) {
            int i = r * GT + t;
            int comp = i >> 9, j = i & 511;
            int row = j >> 2, ch = j & 3;
            CP16(stg + GS_BHI + comp * GS_BLO + row * 80 + ch * 16,
                 tb + comp * 16384 + row * 128 + half * 64 + ch * 16);
        }
    };

    auto COMPUTE = [&](int buf) {
        uint32_t stg = sb + buf * GS_STG;
#pragma unroll
        for (int kk = 0; kk < 2; kk++) {
            int acol = (kk * 16 + (lane >> 4) * 8) * 2;
            uint32_t af[4][2][4];
#pragma unroll
            for (int mt = 0; mt < 4; mt++) {
                uint32_t aaddr = stg + (wm * 64 + mt * 16 + (lane & 15)) * 80 + acol;
                LDSM4(af[mt][0], aaddr);
                LDSM4(af[mt][1], aaddr + GS_ALO);
            }
#pragma unroll
            for (int nt2 = 0; nt2 < 2; nt2++) {
                uint32_t baddr = stg + GS_BHI + (wn * 32 + nt2 * 16 + (lane & 15)) * 80 + acol;
                uint32_t bh[4], bl[4];
                LDSM4(bh, baddr);
                LDSM4(bl, baddr + GS_BLO);
#pragma unroll
                for (int mt = 0; mt < 4; mt++) {
                    MMA_BF16(acc[mt][nt2 * 2],     af[mt][0], bh[0], bh[2]);
                    MMA_BF16(acc[mt][nt2 * 2],     af[mt][0], bl[0], bl[2]);
                    MMA_BF16(acc[mt][nt2 * 2],     af[mt][1], bh[0], bh[2]);
                    MMA_BF16(acc[mt][nt2 * 2 + 1], af[mt][0], bh[1], bh[3]);
                    MMA_BF16(acc[mt][nt2 * 2 + 1], af[mt][0], bl[1], bl[3]);
                    MMA_BF16(acc[mt][nt2 * 2 + 1], af[mt][1], bh[1], bh[3]);
                }
            }
        }
    };

    ISSUE(0); CP_COMMIT();
    ISSUE(1); CP_COMMIT();
    for (int kt = 0; kt < nk; kt++) {
        CP_WAIT1();
        __syncthreads();
        if (kt + 2 < nk) ISSUE(kt + 2);
        CP_COMMIT();
        COMPUTE(kt % 3);
    }

    const int mrow = lane >> 2, ncol = (lane & 3) * 2;
#pragma unroll
    for (int mt = 0; mt < 4; mt++) {
#pragma unroll
        for (int nb = 0; nb < 4; nb++) {
            int c = bn + wn * 32 + nb * 8 + ncol;
            float2 bi = *(const float2*)(bias + c);
#pragma unroll
            for (int h = 0; h < 2; h++) {
                int m = bm + wm * 64 + mt * 16 + mrow + h * 8;
                float2 v;
                v.x = (acc[mt][nb][h * 2 + 0] + bi.x) * scale;
                v.y = (acc[mt][nb][h * 2 + 1] + bi.y) * scale;
                if (OMODE == 0) {
                    *(float2*)(Cf + (size_t)m * N + c) = v;
                } else {
                    size_t idx = (((size_t)(((m >> 10) << 3) + (c >> 6))) << 16)
                               + ((m & 1023) << 6) + (c & 63);
                    uint32_t hi, lo;
                    split2(v.x, v.y, hi, lo);
                    ((uint32_t*)Chi)[idx >> 1] = hi;
                    ((uint32_t*)Clo)[idx >> 1] = lo;
                }
            }
        }
    }
}

// --- fp16 2-term HMMA GEMM for FFN (A single fp16, B fp16 hi/lo) -------------
#define HS_BHI 20480
#define HS_BLO 10240
#define HS_STG 40960
#define HSMEM_DYN (3*HS_STG)

// OMODE 0: fp32 rowmajor.  OMODE 2: fp16 single rowmajor (+ReLU path).
template<bool RELU, int OMODE>
__global__ __launch_bounds__(GT, 1)
void hmma_gemm_h(const __half* __restrict__ A, const __half* __restrict__ Bt,
                 const float* __restrict__ bias, float* __restrict__ Cf,
                 __half* __restrict__ Ch, int M, int N, int K) {
    extern __shared__ char smbuf[];
    uint32_t sb = smem_u32(smbuf);
    const int t = threadIdx.x, lane = t & 31, wid = t >> 5;
    const int wm = wid & 3, wn = wid >> 2;
    const int bm = blockIdx.y * 256, bn = blockIdx.x * 128;
    const int nk = K >> 5;
    const int ktile_n = K >> 6;

    float acc[4][4][4];
#pragma unroll
    for (int a = 0; a < 4; a++)
#pragma unroll
        for (int b = 0; b < 4; b++)
#pragma unroll
            for (int c = 0; c < 4; c++) acc[a][b][c] = 0.f;

    auto ISSUE = [&](int kt) {
        uint32_t stg = sb + (kt % 3) * HS_STG;
#pragma unroll
        for (int r = 0; r < 2; r++) {
            int i = r * GT + t;
            int row = i >> 2, ch = i & 3;
            const char* src = (const char*)A + (((size_t)(bm + row) * K + kt * 32 + ch * 8) << 1);
            CP16(stg + row * 80 + ch * 16, src);
        }
        const char* tb = (const char*)(Bt + ((size_t)blockIdx.x * ktile_n + (kt >> 1)) * TILE_ELEMS);
        int half = kt & 1;
#pragma unroll
        for (int r = 0; r < 2; r++) {
            int i = r * GT + t;
            int comp = i >> 9, j = i & 511;
            int row = j >> 2, ch = j & 3;
            CP16(stg + HS_BHI + comp * HS_BLO + row * 80 + ch * 16,
                 tb + comp * 16384 + row * 128 + half * 64 + ch * 16);
        }
    };

    auto COMPUTE = [&](int buf) {
        uint32_t stg = sb + buf * HS_STG;
#pragma unroll
        for (int kk = 0; kk < 2; kk++) {
            int acol = (kk * 16 + (lane >> 4) * 8) * 2;
            uint32_t af[4][4];
#pragma unroll
            for (int mt = 0; mt < 4; mt++) {
                LDSM4(af[mt], stg + (wm * 64 + mt * 16 + (lane & 15)) * 80 + acol);
            }
#pragma unroll
            for (int nt2 = 0; nt2 < 2; nt2++) {
                uint32_t baddr = stg + HS_BHI + (wn * 32 + nt2 * 16 + (lane & 15)) * 80 + acol;
                uint32_t bh[4], bl[4];
                LDSM4(bh, baddr);
                LDSM4(bl, baddr + HS_BLO);
#pragma unroll
                for (int mt = 0; mt < 4; mt++) {
                    MMA_F16(acc[mt][nt2 * 2],     af[mt], bh[0], bh[2]);
                    MMA_F16(acc[mt][nt2 * 2],     af[mt], bl[0], bl[2]);
                    MMA_F16(acc[mt][nt2 * 2 + 1], af[mt], bh[1], bh[3]);
                    MMA_F16(acc[mt][nt2 * 2 + 1], af[mt], bl[1], bl[3]);
                }
            }
        }
    };

    ISSUE(0); CP_COMMIT();
    ISSUE(1); CP_COMMIT();
    for (int kt = 0; kt < nk; kt++) {
        CP_WAIT1();
        __syncthreads();
        if (kt + 2 < nk) ISSUE(kt + 2);
        CP_COMMIT();
        COMPUTE(kt % 3);
    }

    const int mrow = lane >> 2, ncol = (lane & 3) * 2;
#pragma unroll
    for (int mt = 0; mt < 4; mt++) {
#pragma unroll
        for (int nb = 0; nb < 4; nb++) {
            int c = bn + wn * 32 + nb * 8 + ncol;
            float2 bi = *(const float2*)(bias + c);
#pragma unroll
            for (int h = 0; h < 2; h++) {
                int m = bm + wm * 64 + mt * 16 + mrow + h * 8;
                float2 v;
                v.x = acc[mt][nb][h * 2 + 0] + bi.x;
                v.y = acc[mt][nb][h * 2 + 1] + bi.y;
                if (RELU) { v.x = fmaxf(v.x, 0.f); v.y = fmaxf(v.y, 0.f); }
                if (OMODE == 0) {
                    *(float2*)(Cf + (size_t)m * N + c) = v;
                } else {
                    ((uint32_t*)Ch)[((size_t)m * N + c) >> 1] = h2pack(v.x, v.y);
                }
            }
        }
    }
}

// ---------------- HMMA flash attention (unchanged, bf16x3) -------------------
#define AQ_LO  18432
#define KVB    36864
#define KV_STG 36864
#define KV_KL  9216
#define KV_VH  18432
#define ATT_SMEM (36864 + 3*36864)

__global__ __launch_bounds__(256)
void attn_hmma(const __nv_bfloat16* __restrict__ Qh, const __nv_bfloat16* __restrict__ Ql,
               const __nv_bfloat16* __restrict__ Kh, const __nv_bfloat16* __restrict__ Kl,
               const __nv_bfloat16* __restrict__ Vh, const __nv_bfloat16* __restrict__ Vl,
               __nv_bfloat16* __restrict__ Oh, __nv_bfloat16* __restrict__ Ol) {
    extern __shared__ char smbuf[];
    uint32_t sb = smem_u32(smbuf);
    const int t = threadIdx.x, lane = t & 31, w = t >> 5;
    const int bh = blockIdx.x;
    const int qbase = blockIdx.y * 128;

    auto ISSUEKV = [&](int c) {
        uint32_t stg = sb + KVB + (c % 3) * KV_STG;
        int kc = c * 64;
#pragma unroll
        for (int r = 0; r < 8; r++) {
            int i = r * 256 + t;
            int ts = i >> 10;
            int j = i & 1023;
            int comp = j >> 9;
            int jj = j & 511;
            int row = jj >> 3, ch = jj & 7;
            const char* base = ts ? (const char*)(comp ? Vl : Vh)
                                  : (const char*)(comp ? Kl : Kh);
            const char* src = base + (((size_t)(bh * SS + kc + row) * DK + ch * 8) << 1);
            CP16(stg + ts * 18432 + comp * 9216 + row * 144 + ch * 16, src);
        }
    };

    ISSUEKV(0); CP_COMMIT();
    ISSUEKV(1); CP_COMMIT();

#pragma unroll
    for (int r = 0; r < 8; r++) {
        int i = r * 256 + t;
        int comp = i >> 10;
        int j = i & 1023;
        int row = j >> 3, ch = j & 7;
        const char* src = (comp ? (const char*)Ql : (const char*)Qh)
                        + (((size_t)(bh * SS + qbase + row) * DK + ch * 8) << 1);
        *(uint4*)(smbuf + comp * AQ_LO + row * 144 + ch * 16) = *(const uint4*)src;
    }
    __syncthreads();

    uint32_t qh[4][4], ql[4][4];
#pragma unroll
    for (int kb = 0; kb < 4; kb++) {
        uint32_t addr = sb + (w * 16 + (lane & 15)) * 144 + (kb * 16 + (lane >> 4) * 8) * 2;
        LDSM4(qh[kb], addr);
        LDSM4(ql[kb], addr + AQ_LO);
    }

    float o[8][4];
#pragma unroll
    for (int i = 0; i < 8; i++)
#pragma unroll
        for (int j = 0; j < 4; j++) o[i][j] = 0.f;
    float m0 = -1.0e30f, m1 = -1.0e30f, l0 = 0.f, l1 = 0.f;

    for (int c = 0; c < SS / 64; c++) {
        CP_WAIT1();
        __syncthreads();
        if (c + 2 < SS / 64) ISSUEKV(c + 2);
        CP_COMMIT();
        uint32_t stg = sb + KVB + (c % 3) * KV_STG;

        float s[8][4];
#pragma unroll
        for (int i = 0; i < 8; i++)
#pragma unroll
            for (int j = 0; j < 4; j++) s[i][j] = 0.f;
#pragma unroll
        for (int kvb = 0; kvb < 4; kvb++) {
#pragma unroll
            for (int kb = 0; kb < 4; kb++) {
                uint32_t addr = stg + (kvb * 16 + (lane & 15)) * 144 + (kb * 16 + (lane >> 4) * 8) * 2;
                uint32_t kfh[4], kfl[4];
                LDSM4(kfh, addr);
                LDSM4(kfl, addr + KV_KL);
                MMA_BF16(s[kvb * 2],     qh[kb], kfh[0], kfh[2]);
                MMA_BF16(s[kvb * 2],     qh[kb], kfl[0], kfl[2]);
                MMA_BF16(s[kvb * 2],     ql[kb], kfh[0], kfh[2]);
                MMA_BF16(s[kvb * 2 + 1], qh[kb], kfh[1], kfh[3]);
                MMA_BF16(s[kvb * 2 + 1], qh[kb], kfl[1], kfl[3]);
                MMA_BF16(s[kvb * 2 + 1], ql[kb], kfh[1], kfh[3]);
            }
        }

        float cm0 = -1.0e30f, cm1 = -1.0e30f;
#pragma unroll
        for (int nb = 0; nb < 8; nb++) {
            cm0 = fmaxf(cm0, fmaxf(s[nb][0], s[nb][1]));
            cm1 = fmaxf(cm1, fmaxf(s[nb][2], s[nb][3]));
        }
        cm0 = fmaxf(cm0, __shfl_xor_sync(0xffffffffu, cm0, 1));
        cm0 = fmaxf(cm0, __shfl_xor_sync(0xffffffffu, cm0, 2));
        cm1 = fmaxf(cm1, __shfl_xor_sync(0xffffffffu, cm1, 1));
        cm1 = fmaxf(cm1, __shfl_xor_sync(0xffffffffu, cm1, 2));
        float m0n = fmaxf(m0, cm0), m1n = fmaxf(m1, cm1);
        float c0 = fexp(m0 - m0n), c1 = fexp(m1 - m1n);
#pragma unroll
        for (int nb = 0; nb < 8; nb++) {
            o[nb][0] *= c0; o[nb][1] *= c0;
            o[nb][2] *= c1; o[nb][3] *= c1;
        }
        float ls0 = 0.f, ls1 = 0.f;
#pragma unroll
        for (int nb = 0; nb < 8; nb++) {
            s[nb][0] = fexp(s[nb][0] - m0n);
            s[nb][1] = fexp(s[nb][1] - m0n);
            s[nb][2] = fexp(s[nb][2] - m1n);
            s[nb][3] = fexp(s[nb][3] - m1n);
            ls0 += s[nb][0] + s[nb][1];
            ls1 += s[nb][2] + s[nb][3];
        }
        ls0 += __shfl_xor_sync(0xffffffffu, ls0, 1);
        ls0 += __shfl_xor_sync(0xffffffffu, ls0, 2);
        ls1 += __shfl_xor_sync(0xffffffffu, ls1, 1);
        ls1 += __shfl_xor_sync(0xffffffffu, ls1, 2);
        l0 = l0 * c0 + ls0;
        l1 = l1 * c1 + ls1;
        m0 = m0n; m1 = m1n;

#pragma unroll
        for (int kb = 0; kb < 4; kb++) {
            uint32_t ph[4], pl[4];
            split2(s[2 * kb][0],     s[2 * kb][1],     ph[0], pl[0]);
            split2(s[2 * kb][2],     s[2 * kb][3],     ph[1], pl[1]);
            split2(s[2 * kb + 1][0], s[2 * kb + 1][1], ph[2], pl[2]);
            split2(s[2 * kb + 1][2], s[2 * kb + 1][3], ph[3], pl[3]);
#pragma unroll
            for (int db = 0; db < 4; db++) {
                uint32_t addr = stg + KV_VH + (kb * 16 + (lane & 15)) * 144 + (db * 16 + (lane >> 4) * 8) * 2;
                uint32_t vfh[4], vfl[4];
                LDSM4T(vfh, addr);
                LDSM4T(vfl, addr + KV_KL);
                MMA_BF16(o[db * 2],     ph, vfh[0], vfh[1]);
                MMA_BF16(o[db * 2],     ph, vfl[0], vfl[1]);
                MMA_BF16(o[db * 2],     pl, vfh[0], vfh[1]);
                MMA_BF16(o[db * 2 + 1], ph, vfh[2], vfh[3]);
                MMA_BF16(o[db * 2 + 1], ph, vfl[2], vfl[3]);
                MMA_BF16(o[db * 2 + 1], pl, vfh[2], vfh[3]);
            }
        }
    }

    float inv0 = 1.f / l0, inv1 = 1.f / l1;
    int r0 = qbase + w * 16 + (lane >> 2);
    int c0c = (lane & 3) * 2;
#pragma unroll
    for (int db = 0; db < 8; db++) {
        int c = db * 8 + c0c;
        uint32_t hi, lo;
        size_t idx0 = ((size_t)bh * SS + r0) * DK + c;
        split2(o[db][0] * inv0, o[db][1] * inv0, hi, lo);
        ((uint32_t*)Oh)[idx0 >> 1] = hi;
        ((uint32_t*)Ol)[idx0 >> 1] = lo;
        size_t idx1 = ((size_t)bh * SS + r0 + 8) * DK + c;
        split2(o[db][2] * inv1, o[db][3] * inv1, hi, lo);
        ((uint32_t*)Oh)[idx1 >> 1] = hi;
        ((uint32_t*)Ol)[idx1 >> 1] = lo;
    }
}

// ---------------- LayerNorm ----------------
template<bool ADD, bool SPLIT>
__global__ __launch_bounds__(128)
void ln_kernel(const float* __restrict__ src, const float* __restrict__ gamma,
               const float* __restrict__ beta, float* __restrict__ xio,
               __nv_bfloat16* __restrict__ xh, __nv_bfloat16* __restrict__ xl,
               __half* __restrict__ xf, float eps) {
    int row = blockIdx.x;
    int t = threadIdx.x;
    int lane = t & 31, wid = t >> 5;
    const float4* sp = (const float4*)(src + (size_t)row * DD);
    float4 v = sp[t];

    __shared__ float red[4];
    __shared__ float bsum, bvar;

    float s = (v.x + v.y) + (v.z + v.w);
#pragma unroll
    for (int o = 16; o > 0; o >>= 1) s += __shfl_xor_sync(0xffffffffu, s, o);
    if (lane == 0) red[wid] = s;
    __syncthreads();
    if (t == 0) bsum = (red[0] + red[1]) + (red[2] + red[3]);
    __syncthreads();
    float mu = bsum * (1.f / DD);

    float dx = v.x - mu, dy = v.y - mu, dz = v.z - mu, dw = v.w - mu;
    float s2 = (dx * dx + dy * dy) + (dz * dz + dw * dw);
#pragma unroll
    for (int o = 16; o > 0; o >>= 1) s2 += __shfl_xor_sync(0xffffffffu, s2, o);
    if (lane == 0) red[wid] = s2;
    __syncthreads();
    if (t == 0) bvar = (red[0] + red[1]) + (red[2] + red[3]);
    __syncthreads();
    float rstd = rsqrtf(bvar * (1.f / DD) + eps);

    int c = t * 4;
    float4 g = *(const float4*)(gamma + c);
    float4 b = *(const float4*)(beta + c);
    float4 o4;
    o4.x = dx * rstd * g.x + b.x;
    o4.y = dy * rstd * g.y + b.y;
    o4.z = dz * rstd * g.z + b.z;
    o4.w = dw * rstd * g.w + b.w;
    float4* xp = (float4*)(xio + (size_t)row * DD);
    if (ADD) {
        float4 xo = xp[t];
        o4.x += xo.x; o4.y += xo.y; o4.z += xo.z; o4.w += xo.w;
    }
    xp[t] = o4;
    if (SPLIT) {
        size_t pidx = ((size_t)row * DD + c) >> 1;
        uint32_t hi, lo;
        split2(o4.x, o4.y, hi, lo);
        ((uint32_t*)xh)[pidx] = hi; ((uint32_t*)xl)[pidx] = lo;
        split2(o4.z, o4.w, hi, lo);
        ((uint32_t*)xh)[pidx + 1] = hi; ((uint32_t*)xl)[pidx + 1] = lo;
        ((uint32_t*)xf)[pidx]     = h2pack(o4.x, o4.y);
        ((uint32_t*)xf)[pidx + 1] = h2pack(o4.z, o4.w);
    }
}

// ---------------- driver ----------------
extern "C" void kernel_launch(void* const* d_in, const int* in_sizes, int n_in,
                              void* d_out, int out_size) {
    const float* src  = (const float*)d_in[0];
    const float* Wq   = (const float*)d_in[1];
    const float* bq   = (const float*)d_in[2];
    const float* Wk   = (const float*)d_in[3];
    const float* bk   = (const float*)d_in[4];
    const float* Wv   = (const float*)d_in[5];
    const float* bv   = (const float*)d_in[6];
    const float* Wo   = (const float*)d_in[7];
    const float* bo   = (const float*)d_in[8];
    const float* ln1g = (const float*)d_in[9];
    const float* ln1b = (const float*)d_in[10];
    const float* W1   = (const float*)d_in[11];
    const float* b1   = (const float*)d_in[12];
    const float* W2   = (const float*)d_in[13];
    const float* b2   = (const float*)d_in[14];
    const float* ln2g = (const float*)d_in[15];
    const float* ln2b = (const float*)d_in[16];
    const float* lnfg = (const float*)d_in[17];
    const float* lnfb = (const float*)d_in[18];
    float* out = (float*)d_out;

    float *px, *pt;
    __nv_bfloat16 *xs, *qs, *ks, *vs, *os;
    __half *xf, *ff, *w1h, *w2h;
    __nv_bfloat16 *wqs, *wks, *wvs, *wos;
    cudaGetSymbolAddress((void**)&px, g_x);
    cudaGetSymbolAddress((void**)&pt, g_t);
    cudaGetSymbolAddress((void**)&xs, g_xs);
    cudaGetSymbolAddress((void**)&qs, g_qs);
    cudaGetSymbolAddress((void**)&ks, g_ks);
    cudaGetSymbolAddress((void**)&vs, g_vs);
    cudaGetSymbolAddress((void**)&os, g_os);
    cudaGetSymbolAddress((void**)&xf, g_xf);
    cudaGetSymbolAddress((void**)&ff, g_ff);
    cudaGetSymbolAddress((void**)&wqs, g_wq_s);
    cudaGetSymbolAddress((void**)&wks, g_wk_s);
    cudaGetSymbolAddress((void**)&wvs, g_wv_s);
    cudaGetSymbolAddress((void**)&wos, g_wo_s);
    cudaGetSymbolAddress((void**)&w1h, g_w1h);
    cudaGetSymbolAddress((void**)&w2h, g_w2h);

    __nv_bfloat16 *xh = xs, *xl = xs + (size_t)NN * DD;
    __nv_bfloat16 *qh = qs, *ql = qs + (size_t)NN * DD;
    __nv_bfloat16 *kh = ks, *kl = ks + (size_t)NN * DD;
    __nv_bfloat16 *vh = vs, *vl = vs + (size_t)NN * DD;
    __nv_bfloat16 *oh = os, *ol = os + (size_t)NN * DD;

    cudaFuncSetAttribute(hmma_gemm<0,1>,       cudaFuncAttributeMaxDynamicSharedMemorySize, SMEM_DYN);
    cudaFuncSetAttribute(hmma_gemm<1,0>,       cudaFuncAttributeMaxDynamicSharedMemorySize, SMEM_DYN);
    cudaFuncSetAttribute(hmma_gemm_h<true,2>,  cudaFuncAttributeMaxDynamicSharedMemorySize, HSMEM_DYN);
    cudaFuncSetAttribute(hmma_gemm_h<false,0>, cudaFuncAttributeMaxDynamicSharedMemorySize, HSMEM_DYN);
    cudaFuncSetAttribute(attn_hmma, cudaFuncAttributeMaxDynamicSharedMemorySize, ATT_SMEM);

    split_all_kernel<<<2304, 256>>>(Wq, Wk, Wv, Wo, W1, W2, wqs, wks, wvs, wos, w1h, w2h);
    add_pe_kernel<<<(NN * DD / 2 + 255) / 256, 256>>>(src, px, xh, xl, xf);

    dim3 gProj(4, 32);
    dim3 gFfn1(16, 32);
    dim3 gAttn(BB * HH, SS / 128);

    for (int l = 0; l < LAY; l++) {
        size_t ws_proj = (size_t)l * 4 * 8 * TILE_ELEMS;
        size_t ws_w1   = (size_t)l * 16 * 8 * TILE_ELEMS;
        size_t ws_w2   = (size_t)l * 4 * 32 * TILE_ELEMS;

        hmma_gemm<0,1><<<gProj, GT, SMEM_DYN>>>(xh, xl, wqs + ws_proj, bq + l * HH * DK,
                                                nullptr, qh, ql, NN, DD, DD, 0.125f);
        hmma_gemm<0,1><<<gProj, GT, SMEM_DYN>>>(xh, xl, wks + ws_proj, bk + l * HH * DK,
                                                nullptr, kh, kl, NN, DD, DD, 1.0f);
        hmma_gemm<0,1><<<gProj, GT, SMEM_DYN>>>(xh, xl, wvs + ws_proj, bv + l * HH * DK,
                                                nullptr, vh, vl, NN, DD, DD, 1.0f);

        attn_hmma<<<gAttn, 256, ATT_SMEM>>>(qh, ql, kh, kl, vh, vl, oh, ol);

        hmma_gemm<1,0><<<gProj, GT, SMEM_DYN>>>(oh, ol, wos + ws_proj, bo + l * DD,
                                                pt, nullptr, nullptr, NN, DD, DD, 1.0f);
        ln_kernel<true,true><<<NN, 128>>>(pt, ln1g + l * DD, ln1b + l * DD, px, xh, xl, xf, 1e-5f);

        hmma_gemm_h<true,2><<<gFfn1, GT, HSMEM_DYN>>>(xf, w1h + ws_w1, b1 + l * DFF,
                                                      nullptr, ff, NN, DFF, DD);
        hmma_gemm_h<false,0><<<gProj, GT, HSMEM_DYN>>>(ff, w2h + ws_w2, b2 + l * DD,
                                                       pt, nullptr, NN, DD, DFF);
        ln_kernel<true,true><<<NN, 128>>>(pt, ln2g + l * DD, ln2b + l * DD, px, xh, xl, xf, 1e-5f);
    }

    ln_kernel<false,false><<<NN, 128>>>(px, lnfg, lnfb, out, nullptr, nullptr, nullptr, 1e-6f);
}

// round 16
// speedup vs baseline: 1.3212x; 1.1053x over previous
// rev: r16-resubmit of all-GEMM fp16 2-term (identical to r15 modulo this marker)
#include <cuda_runtime.h>
#include <cuda_bf16.h>
#include <cuda_fp16.h>
#include <math.h>
#include <stdint.h>

#define LAY 6
#define HH  8
#define DD  512
#define DK  64
#define DFF 2048
#define BB  8
#define SS  1024
#define NN  (BB*SS)

// ---------------- scratch ----------------
__device__ float g_x[NN*DD];
__device__ float g_t[NN*DD];
__device__ __half        g_xf[NN*DD];       // fp16 single x (GEMM A)
__device__ __half        g_ff[NN*DFF];      // fp16 single ffn hidden
__device__ __half        g_of[NN*DD];       // fp16 single attention out (bhsk)
__device__ __nv_bfloat16 g_qs[2*NN*DD];     // bf16 hi/lo for attention
__device__ __nv_bfloat16 g_ks[2*NN*DD];
__device__ __nv_bfloat16 g_vs[2*NN*DD];

#define TILE_ELEMS 16384
__device__ __half g_wq_h[LAY*4*8*TILE_ELEMS];
__device__ __half g_wk_h[LAY*4*8*TILE_ELEMS];
__device__ __half g_wv_h[LAY*4*8*TILE_ELEMS];
__device__ __half g_wo_h[LAY*4*8*TILE_ELEMS];
__device__ __half g_w1h[LAY*16*8*TILE_ELEMS];
__device__ __half g_w2h[LAY*4*32*TILE_ELEMS];

// ---------------- PTX helpers ----------------
__device__ __forceinline__ uint32_t smem_u32(const void* p) {
    uint32_t a;
    asm("{ .reg .u64 t; cvta.to.shared.u64 t, %1; cvt.u32.u64 %0, t; }" : "=r"(a) : "l"(p));
    return a;
}
#define LDSM4(r, a) \
    asm volatile("ldmatrix.sync.aligned.m8n8.x4.shared.b16 {%0,%1,%2,%3}, [%4];" \
        : "=r"((r)[0]), "=r"((r)[1]), "=r"((r)[2]), "=r"((r)[3]) : "r"(a))
#define LDSM4T(r, a) \
    asm volatile("ldmatrix.sync.aligned.m8n8.x4.trans.shared.b16 {%0,%1,%2,%3}, [%4];" \
        : "=r"((r)[0]), "=r"((r)[1]), "=r"((r)[2]), "=r"((r)[3]) : "r"(a))
#define MMA_BF16(d, a, b0, b1) \
    asm volatile("mma.sync.aligned.m16n8k16.row.col.f32.bf16.bf16.f32 " \
        "{%0,%1,%2,%3}, {%4,%5,%6,%7}, {%8,%9}, {%0,%1,%2,%3};" \
        : "+f"((d)[0]), "+f"((d)[1]), "+f"((d)[2]), "+f"((d)[3]) \
        : "r"((a)[0]), "r"((a)[1]), "r"((a)[2]), "r"((a)[3]), "r"(b0), "r"(b1))
#define MMA_F16(d, a, b0, b1) \
    asm volatile("mma.sync.aligned.m16n8k16.row.col.f32.f16.f16.f32 " \
        "{%0,%1,%2,%3}, {%4,%5,%6,%7}, {%8,%9}, {%0,%1,%2,%3};" \
        : "+f"((d)[0]), "+f"((d)[1]), "+f"((d)[2]), "+f"((d)[3]) \
        : "r"((a)[0]), "r"((a)[1]), "r"((a)[2]), "r"((a)[3]), "r"(b0), "r"(b1))
#define CP16(dst, src) \
    asm volatile("cp.async.cg.shared.global [%0], [%1], 16;" :: "r"(dst), "l"(src))
#define CP_COMMIT() asm volatile("cp.async.commit_group;" ::: "memory")
#define CP_WAIT1()  asm volatile("cp.async.wait_group 1;" ::: "memory")

__device__ __forceinline__ float fexp(float x) {
    float t = x * 1.44269504f;
    t = fmaxf(t, -126.0f);
    float i = rintf(t);
    float f = t - i;
    float p =       1.54035304e-4f;
    p = fmaf(p, f, 1.33335581e-3f);
    p = fmaf(p, f, 9.61812910e-3f);
    p = fmaf(p, f, 5.55041086e-2f);
    p = fmaf(p, f, 2.40226507e-1f);
    p = fmaf(p, f, 6.93147182e-1f);
    p = fmaf(p, f, 1.0f);
    return p * __int_as_float(((int)i + 127) << 23);
}

__device__ __forceinline__ void split2(float a, float b, uint32_t& hi, uint32_t& lo) {
    __nv_bfloat162 h = __floats2bfloat162_rn(a, b);
    __nv_bfloat162 l = __floats2bfloat162_rn(a - __bfloat162float(h.x),
                                             b - __bfloat162float(h.y));
    hi = *(uint32_t*)&h;
    lo = *(uint32_t*)&l;
}
__device__ __forceinline__ void split2h(float a, float b, uint32_t& hi, uint32_t& lo) {
    __half2 h = __floats2half2_rn(a, b);
    __half2 l = __floats2half2_rn(a - __half2float(__low2half(h)),
                                  b - __half2float(__high2half(h)));
    hi = *(uint32_t*)&h;
    lo = *(uint32_t*)&l;
}
__device__ __forceinline__ uint32_t h2pack(float a, float b) {
    __half2 h = __floats2half2_rn(a, b);
    return *(uint32_t*)&h;
}

// ---------------- weight pre-split: ALL weights fp16 hi/lo ----------------
__device__ __forceinline__ void split_tile_h(const float* __restrict__ W,
                                             __half* __restrict__ out,
                                             int K, int N, int blocked, int tile,
                                             float (*s)[65]) {
    int kt = tile % (K >> 6);
    int rest = tile / (K >> 6);
    int nt = rest % (N >> 7);
    int l = rest / (N >> 7);
    int n0 = nt << 7, k0 = kt << 6;
    int t = threadIdx.x;
#pragma unroll
    for (int r = 0; r < 32; r++) {
        int i = r * 256 + t;
        int k = i >> 7, n = i & 127;
        float x;
        if (blocked) x = W[(((size_t)l * HH + ((n0 + n) >> 6)) * DD + k0 + k) * DK + ((n0 + n) & 63)];
        else         x = W[((size_t)l * K + k0 + k) * N + n0 + n];
        s[n][k] = x;
    }
    __syncthreads();
    uint32_t* oh = (uint32_t*)(out + (size_t)tile * TILE_ELEMS);
    uint32_t* ol = oh + 4096;
#pragma unroll
    for (int r = 0; r < 16; r++) {
        int i = r * 256 + t;
        int n = i >> 5, k = (i & 31) << 1;
        uint32_t hi, lo;
        split2h(s[n][k], s[n][k + 1], hi, lo);
        oh[n * 32 + (k >> 1)] = hi;
        ol[n * 32 + (k >> 1)] = lo;
    }
}

__global__ __launch_bounds__(256)
void split_all_kernel(const float* Wq, const float* Wk, const float* Wv,
                      const float* Wo, const float* W1, const float* W2,
                      __half* oq, __half* ok, __half* ov,
                      __half* oo, __half* o1, __half* o2) {
    __shared__ float s[128][65];
    int b = blockIdx.x;
    if      (b < 192)  split_tile_h(Wq, oq, DD,  DD,  1, b,        s);
    else if (b < 384)  split_tile_h(Wk, ok, DD,  DD,  1, b - 192,  s);
    else if (b < 576)  split_tile_h(Wv, ov, DD,  DD,  1, b - 384,  s);
    else if (b < 768)  split_tile_h(Wo, oo, DD,  DD,  0, b - 576,  s);
    else if (b < 1536) split_tile_h(W1, o1, DD,  DFF, 0, b - 768,  s);
    else               split_tile_h(W2, o2, DFF, DD,  0, b - 1536, s);
}

// ---------------- positional encoding ----------------
__global__ void add_pe_kernel(const float* __restrict__ src, float* __restrict__ x,
                              __half* __restrict__ xf) {
    int gid = blockIdx.x * 256 + threadIdx.x;
    if (gid >= NN * DD / 2) return;
    int idx = gid * 2;
    int d = idx & (DD - 1);
    int s = (idx >> 9) & (SS - 1);
    int i = d >> 1;
    double div = exp((double)(2 * i) * (-9.210340371976184 / (double)DD));
    double ang = (double)s * div;
    float v0 = src[idx]     + (float)sin(ang);
    float v1 = src[idx + 1] + (float)cos(ang);
    x[idx] = v0; x[idx + 1] = v1;
    ((uint32_t*)xf)[gid] = h2pack(v0, v1);
}

// --- fp16 2-term HMMA GEMM (256x128 CTA, 16 warps of 64x32, 3-stage) ---------
// stage (40960 B): A 256x(64+16)B @0, B_hi @20480, B_lo @30720
#define HS_BHI 20480
#define HS_BLO 10240
#define HS_STG 40960
#define HSMEM_DYN (3*HS_STG)
#define GT 512

// AMODE 0: A rowmajor fp16.  AMODE 1: A bhsk-gather fp16.
// OMODE 0: fp32 rowmajor.  OMODE 1: split-bf16 bhsk (scaled).  OMODE 2: fp16 rowmajor.
template<int AMODE, int OMODE, bool RELU>
__global__ __launch_bounds__(GT, 1)
void hmma_gemm_h(const __half* __restrict__ A, const __half* __restrict__ Bt,
                 const float* __restrict__ bias, float* __restrict__ Cf,
                 __half* __restrict__ Ch,
                 __nv_bfloat16* __restrict__ Chi, __nv_bfloat16* __restrict__ Clo,
                 int M, int N, int K, float scale) {
    extern __shared__ char smbuf[];
    uint32_t sb = smem_u32(smbuf);
    const int t = threadIdx.x, lane = t & 31, wid = t >> 5;
    const int wm = wid & 3, wn = wid >> 2;
    const int bm = blockIdx.y * 256, bn = blockIdx.x * 128;
    const int nk = K >> 5;
    const int ktile_n = K >> 6;

    float acc[4][4][4];
#pragma unroll
    for (int a = 0; a < 4; a++)
#pragma unroll
        for (int b = 0; b < 4; b++)
#pragma unroll
            for (int c = 0; c < 4; c++) acc[a][b][c] = 0.f;

    auto ISSUE = [&](int kt) {
        uint32_t stg = sb + (kt % 3) * HS_STG;
        // A: 1024 chunks (256 rows x 4)
#pragma unroll
        for (int r = 0; r < 2; r++) {
            int i = r * GT + t;
            int row = i >> 2, ch = i & 3;
            const char* src;
            if (AMODE == 0) {
                src = (const char*)A + (((size_t)(bm + row) * K + kt * 32 + ch * 8) << 1);
            } else {
                int kk = kt * 32 + ch * 8;
                int mm = bm + row;
                src = (const char*)A + (((size_t)(((mm >> 10) << 3) + (kk >> 6))) << 17)
                                     + ((mm & 1023) << 7) + ((kk & 63) << 1);
            }
            CP16(stg + row * 80 + ch * 16, src);
        }
        // B: 1024 chunks (hi/lo x 128 rows x 4)
        const char* tb = (const char*)(Bt + ((size_t)blockIdx.x * ktile_n + (kt >> 1)) * TILE_ELEMS);
        int half = kt & 1;
#pragma unroll
        for (int r = 0; r < 2; r++) {
            int i = r * GT + t;
            int comp = i >> 9, j = i & 511;
            int row = j >> 2, ch = j & 3;
            CP16(stg + HS_BHI + comp * HS_BLO + row * 80 + ch * 16,
                 tb + comp * 16384 + row * 128 + half * 64 + ch * 16);
        }
    };

    auto COMPUTE = [&](int buf) {
        uint32_t stg = sb + buf * HS_STG;
#pragma unroll
        for (int kk = 0; kk < 2; kk++) {
            int acol = (kk * 16 + (lane >> 4) * 8) * 2;
            uint32_t af[4][4];
#pragma unroll
            for (int mt = 0; mt < 4; mt++) {
                LDSM4(af[mt], stg + (wm * 64 + mt * 16 + (lane & 15)) * 80 + acol);
            }
#pragma unroll
            for (int nt2 = 0; nt2 < 2; nt2++) {
                uint32_t baddr = stg + HS_BHI + (wn * 32 + nt2 * 16 + (lane & 15)) * 80 + acol;
                uint32_t bh[4], bl[4];
                LDSM4(bh, baddr);
                LDSM4(bl, baddr + HS_BLO);
#pragma unroll
                for (int mt = 0; mt < 4; mt++) {
                    MMA_F16(acc[mt][nt2 * 2],     af[mt], bh[0], bh[2]);
                    MMA_F16(acc[mt][nt2 * 2],     af[mt], bl[0], bl[2]);
                    MMA_F16(acc[mt][nt2 * 2 + 1], af[mt], bh[1], bh[3]);
                    MMA_F16(acc[mt][nt2 * 2 + 1], af[mt], bl[1], bl[3]);
                }
            }
        }
    };

    ISSUE(0); CP_COMMIT();
    ISSUE(1); CP_COMMIT();
    for (int kt = 0; kt < nk; kt++) {
        CP_WAIT1();
        __syncthreads();
        if (kt + 2 < nk) ISSUE(kt + 2);
        CP_COMMIT();
        COMPUTE(kt % 3);
    }

    const int mrow = lane >> 2, ncol = (lane & 3) * 2;
#pragma unroll
    for (int mt = 0; mt < 4; mt++) {
#pragma unroll
        for (int nb = 0; nb < 4; nb++) {
            int c = bn + wn * 32 + nb * 8 + ncol;
            float2 bi = *(const float2*)(bias + c);
#pragma unroll
            for (int h = 0; h < 2; h++) {
                int m = bm + wm * 64 + mt * 16 + mrow + h * 8;
                float2 v;
                v.x = (acc[mt][nb][h * 2 + 0] + bi.x) * scale;
                v.y = (acc[mt][nb][h * 2 + 1] + bi.y) * scale;
                if (RELU) { v.x = fmaxf(v.x, 0.f); v.y = fmaxf(v.y, 0.f); }
                if (OMODE == 0) {
                    *(float2*)(Cf + (size_t)m * N + c) = v;
                } else if (OMODE == 1) {
                    size_t idx = (((size_t)(((m >> 10) << 3) + (c >> 6))) << 16)
                               + ((m & 1023) << 6) + (c & 63);
                    uint32_t hi, lo;
                    split2(v.x, v.y, hi, lo);
                    ((uint32_t*)Chi)[idx >> 1] = hi;
                    ((uint32_t*)Clo)[idx >> 1] = lo;
                } else {
                    ((uint32_t*)Ch)[((size_t)m * N + c) >> 1] = h2pack(v.x, v.y);
                }
            }
        }
    }
}

// ---------------- HMMA flash attention (bf16x3 internals, fp16 out) ----------
#define AQ_LO  18432
#define KVB    36864
#define KV_STG 36864
#define KV_KL  9216
#define KV_VH  18432
#define ATT_SMEM (36864 + 3*36864)

__global__ __launch_bounds__(256)
void attn_hmma(const __nv_bfloat16* __restrict__ Qh, const __nv_bfloat16* __restrict__ Ql,
               const __nv_bfloat16* __restrict__ Kh, const __nv_bfloat16* __restrict__ Kl,
               const __nv_bfloat16* __restrict__ Vh, const __nv_bfloat16* __restrict__ Vl,
               __half* __restrict__ Of) {
    extern __shared__ char smbuf[];
    uint32_t sb = smem_u32(smbuf);
    const int t = threadIdx.x, lane = t & 31, w = t >> 5;
    const int bh = blockIdx.x;
    const int qbase = blockIdx.y * 128;

    auto ISSUEKV = [&](int c) {
        uint32_t stg = sb + KVB + (c % 3) * KV_STG;
        int kc = c * 64;
#pragma unroll
        for (int r = 0; r < 8; r++) {
            int i = r * 256 + t;
            int ts = i >> 10;
            int j = i & 1023;
            int comp = j >> 9;
            int jj = j & 511;
            int row = jj >> 3, ch = jj & 7;
            const char* base = ts ? (const char*)(comp ? Vl : Vh)
                                  : (const char*)(comp ? Kl : Kh);
            const char* src = base + (((size_t)(bh * SS + kc + row) * DK + ch * 8) << 1);
            CP16(stg + ts * 18432 + comp * 9216 + row * 144 + ch * 16, src);
        }
    };

    ISSUEKV(0); CP_COMMIT();
    ISSUEKV(1); CP_COMMIT();

#pragma unroll
    for (int r = 0; r < 8; r++) {
        int i = r * 256 + t;
        int comp = i >> 10;
        int j = i & 1023;
        int row = j >> 3, ch = j & 7;
        const char* src = (comp ? (const char*)Ql : (const char*)Qh)
                        + (((size_t)(bh * SS + qbase + row) * DK + ch * 8) << 1);
        *(uint4*)(smbuf + comp * AQ_LO + row * 144 + ch * 16) = *(const uint4*)src;
    }
    __syncthreads();

    uint32_t qh[4][4], ql[4][4];
#pragma unroll
    for (int kb = 0; kb < 4; kb++) {
        uint32_t addr = sb + (w * 16 + (lane & 15)) * 144 + (kb * 16 + (lane >> 4) * 8) * 2;
        LDSM4(qh[kb], addr);
        LDSM4(ql[kb], addr + AQ_LO);
    }

    float o[8][4];
#pragma unroll
    for (int i = 0; i < 8; i++)
#pragma unroll
        for (int j = 0; j < 4; j++) o[i][j] = 0.f;
    float m0 = -1.0e30f, m1 = -1.0e30f, l0 = 0.f, l1 = 0.f;

    for (int c = 0; c < SS / 64; c++) {
        CP_WAIT1();
        __syncthreads();
        if (c + 2 < SS / 64) ISSUEKV(c + 2);
        CP_COMMIT();
        uint32_t stg = sb + KVB + (c % 3) * KV_STG;

        float s[8][4];
#pragma unroll
        for (int i = 0; i < 8; i++)
#pragma unroll
            for (int j = 0; j < 4; j++) s[i][j] = 0.f;
#pragma unroll
        for (int kvb = 0; kvb < 4; kvb++) {
#pragma unroll
            for (int kb = 0; kb < 4; kb++) {
                uint32_t addr = stg + (kvb * 16 + (lane & 15)) * 144 + (kb * 16 + (lane >> 4) * 8) * 2;
                uint32_t kfh[4], kfl[4];
                LDSM4(kfh, addr);
                LDSM4(kfl, addr + KV_KL);
                MMA_BF16(s[kvb * 2],     qh[kb], kfh[0], kfh[2]);
                MMA_BF16(s[kvb * 2],     qh[kb], kfl[0], kfl[2]);
                MMA_BF16(s[kvb * 2],     ql[kb], kfh[0], kfh[2]);
                MMA_BF16(s[kvb * 2 + 1], qh[kb], kfh[1], kfh[3]);
                MMA_BF16(s[kvb * 2 + 1], qh[kb], kfl[1], kfl[3]);
                MMA_BF16(s[kvb * 2 + 1], ql[kb], kfh[1], kfh[3]);
            }
        }

        float cm0 = -1.0e30f, cm1 = -1.0e30f;
#pragma unroll
        for (int nb = 0; nb < 8; nb++) {
            cm0 = fmaxf(cm0, fmaxf(s[nb][0], s[nb][1]));
            cm1 = fmaxf(cm1, fmaxf(s[nb][2], s[nb][3]));
        }
        cm0 = fmaxf(cm0, __shfl_xor_sync(0xffffffffu, cm0, 1));
        cm0 = fmaxf(cm0, __shfl_xor_sync(0xffffffffu, cm0, 2));
        cm1 = fmaxf(cm1, __shfl_xor_sync(0xffffffffu, cm1, 1));
        cm1 = fmaxf(cm1, __shfl_xor_sync(0xffffffffu, cm1, 2));
        float m0n = fmaxf(m0, cm0), m1n = fmaxf(m1, cm1);
        float c0 = fexp(m0 - m0n), c1 = fexp(m1 - m1n);
#pragma unroll
        for (int nb = 0; nb < 8; nb++) {
            o[nb][0] *= c0; o[nb][1] *= c0;
            o[nb][2] *= c1; o[nb][3] *= c1;
        }
        float ls0 = 0.f, ls1 = 0.f;
#pragma unroll
        for (int nb = 0; nb < 8; nb++) {
            s[nb][0] = fexp(s[nb][0] - m0n);
            s[nb][1] = fexp(s[nb][1] - m0n);
            s[nb][2] = fexp(s[nb][2] - m1n);
            s[nb][3] = fexp(s[nb][3] - m1n);
            ls0 += s[nb][0] + s[nb][1];
            ls1 += s[nb][2] + s[nb][3];
        }
        ls0 += __shfl_xor_sync(0xffffffffu, ls0, 1);
        ls0 += __shfl_xor_sync(0xffffffffu, ls0, 2);
        ls1 += __shfl_xor_sync(0xffffffffu, ls1, 1);
        ls1 += __shfl_xor_sync(0xffffffffu, ls1, 2);
        l0 = l0 * c0 + ls0;
        l1 = l1 * c1 + ls1;
        m0 = m0n; m1 = m1n;

#pragma unroll
        for (int kb = 0; kb < 4; kb++) {
            uint32_t ph[4], pl[4];
            split2(s[2 * kb][0],     s[2 * kb][1],     ph[0], pl[0]);
            split2(s[2 * kb][2],     s[2 * kb][3],     ph[1], pl[1]);
            split2(s[2 * kb + 1][0], s[2 * kb + 1][1], ph[2], pl[2]);
            split2(s[2 * kb + 1][2], s[2 * kb + 1][3], ph[3], pl[3]);
#pragma unroll
            for (int db = 0; db < 4; db++) {
                uint32_t addr = stg + KV_VH + (kb * 16 + (lane & 15)) * 144 + (db * 16 + (lane >> 4) * 8) * 2;
                uint32_t vfh[4], vfl[4];
                LDSM4T(vfh, addr);
                LDSM4T(vfl, addr + KV_KL);
                MMA_BF16(o[db * 2],     ph, vfh[0], vfh[1]);
                MMA_BF16(o[db * 2],     ph, vfl[0], vfl[1]);
                MMA_BF16(o[db * 2],     pl, vfh[0], vfh[1]);
                MMA_BF16(o[db * 2 + 1], ph, vfh[2], vfh[3]);
                MMA_BF16(o[db * 2 + 1], ph, vfl[2], vfl[3]);
                MMA_BF16(o[db * 2 + 1], pl, vfh[2], vfh[3]);
            }
        }
    }

    float inv0 = 1.f / l0, inv1 = 1.f / l1;
    int r0 = qbase + w * 16 + (lane >> 2);
    int c0c = (lane & 3) * 2;
#pragma unroll
    for (int db = 0; db < 8; db++) {
        int c = db * 8 + c0c;
        size_t idx0 = ((size_t)bh * SS + r0) * DK + c;
        ((uint32_t*)Of)[idx0 >> 1] = h2pack(o[db][0] * inv0, o[db][1] * inv0);
        size_t idx1 = ((size_t)bh * SS + r0 + 8) * DK + c;
        ((uint32_t*)Of)[idx1 >> 1] = h2pack(o[db][2] * inv1, o[db][3] * inv1);
    }
}

// ---------------- LayerNorm ----------------
template<bool ADD, bool SPLIT>
__global__ __launch_bounds__(128)
void ln_kernel(const float* __restrict__ src, const float* __restrict__ gamma,
               const float* __restrict__ beta, float* __restrict__ xio,
               __half* __restrict__ xf, float eps) {
    int row = blockIdx.x;
    int t = threadIdx.x;
    int lane = t & 31, wid = t >> 5;
    const float4* sp = (const float4*)(src + (size_t)row * DD);
    float4 v = sp[t];

    __shared__ float red[4];
    __shared__ float bsum, bvar;

    float s = (v.x + v.y) + (v.z + v.w);
#pragma unroll
    for (int o = 16; o > 0; o >>= 1) s += __shfl_xor_sync(0xffffffffu, s, o);
    if (lane == 0) red[wid] = s;
    __syncthreads();
    if (t == 0) bsum = (red[0] + red[1]) + (red[2] + red[3]);
    __syncthreads();
    float mu = bsum * (1.f / DD);

    float dx = v.x - mu, dy = v.y - mu, dz = v.z - mu, dw = v.w - mu;
    float s2 = (dx * dx + dy * dy) + (dz * dz + dw * dw);
#pragma unroll
    for (int o = 16; o > 0; o >>= 1) s2 += __shfl_xor_sync(0xffffffffu, s2, o);
    if (lane == 0) red[wid] = s2;
    __syncthreads();
    if (t == 0) bvar = (red[0] + red[1]) + (red[2] + red[3]);
    __syncthreads();
    float rstd = rsqrtf(bvar * (1.f / DD) + eps);

    int c = t * 4;
    float4 g = *(const float4*)(gamma + c);
    float4 b = *(const float4*)(beta + c);
    float4 o4;
    o4.x = dx * rstd * g.x + b.x;
    o4.y = dy * rstd * g.y + b.y;
    o4.z = dz * rstd * g.z + b.z;
    o4.w = dw * rstd * g.w + b.w;
    float4* xp = (float4*)(xio + (size_t)row * DD);
    if (ADD) {
        float4 xo = xp[t];
        o4.x += xo.x; o4.y += xo.y; o4.z += xo.z; o4.w += xo.w;
    }
    xp[t] = o4;
    if (SPLIT) {
        size_t pidx = ((size_t)row * DD + c) >> 1;
        ((uint32_t*)xf)[pidx]     = h2pack(o4.x, o4.y);
        ((uint32_t*)xf)[pidx + 1] = h2pack(o4.z, o4.w);
    }
}

// ---------------- driver ----------------
extern "C" void kernel_launch(void* const* d_in, const int* in_sizes, int n_in,
                              void* d_out, int out_size) {
    const float* src  = (const float*)d_in[0];
    const float* Wq   = (const float*)d_in[1];
    const float* bq   = (const float*)d_in[2];
    const float* Wk   = (const float*)d_in[3];
    const float* bk   = (const float*)d_in[4];
    const float* Wv   = (const float*)d_in[5];
    const float* bv   = (const float*)d_in[6];
    const float* Wo   = (const float*)d_in[7];
    const float* bo   = (const float*)d_in[8];
    const float* ln1g = (const float*)d_in[9];
    const float* ln1b = (const float*)d_in[10];
    const float* W1   = (const float*)d_in[11];
    const float* b1   = (const float*)d_in[12];
    const float* W2   = (const float*)d_in[13];
    const float* b2   = (const float*)d_in[14];
    const float* ln2g = (const float*)d_in[15];
    const float* ln2b = (const float*)d_in[16];
    const float* lnfg = (const float*)d_in[17];
    const float* lnfb = (const float*)d_in[18];
    float* out = (float*)d_out;

    float *px, *pt;
    __nv_bfloat16 *qs, *ks, *vs;
    __half *xf, *ff, *of, *wqh, *wkh, *wvh, *woh, *w1h, *w2h;
    cudaGetSymbolAddress((void**)&px, g_x);
    cudaGetSymbolAddress((void**)&pt, g_t);
    cudaGetSymbolAddress((void**)&qs, g_qs);
    cudaGetSymbolAddress((void**)&ks, g_ks);
    cudaGetSymbolAddress((void**)&vs, g_vs);
    cudaGetSymbolAddress((void**)&xf, g_xf);
    cudaGetSymbolAddress((void**)&ff, g_ff);
    cudaGetSymbolAddress((void**)&of, g_of);
    cudaGetSymbolAddress((void**)&wqh, g_wq_h);
    cudaGetSymbolAddress((void**)&wkh, g_wk_h);
    cudaGetSymbolAddress((void**)&wvh, g_wv_h);
    cudaGetSymbolAddress((void**)&woh, g_wo_h);
    cudaGetSymbolAddress((void**)&w1h, g_w1h);
    cudaGetSymbolAddress((void**)&w2h, g_w2h);

    __nv_bfloat16 *qh = qs, *ql = qs + (size_t)NN * DD;
    __nv_bfloat16 *kh = ks, *kl = ks + (size_t)NN * DD;
    __nv_bfloat16 *vh = vs, *vl = vs + (size_t)NN * DD;

    cudaFuncSetAttribute(hmma_gemm_h<0,1,false>, cudaFuncAttributeMaxDynamicSharedMemorySize, HSMEM_DYN);
    cudaFuncSetAttribute(hmma_gemm_h<1,0,false>, cudaFuncAttributeMaxDynamicSharedMemorySize, HSMEM_DYN);
    cudaFuncSetAttribute(hmma_gemm_h<0,2,true >, cudaFuncAttributeMaxDynamicSharedMemorySize, HSMEM_DYN);
    cudaFuncSetAttribute(hmma_gemm_h<0,0,false>, cudaFuncAttributeMaxDynamicSharedMemorySize, HSMEM_DYN);
    cudaFuncSetAttribute(attn_hmma, cudaFuncAttributeMaxDynamicSharedMemorySize, ATT_SMEM);

    split_all_kernel<<<2304, 256>>>(Wq, Wk, Wv, Wo, W1, W2, wqh, wkh, wvh, woh, w1h, w2h);
    add_pe_kernel<<<(NN * DD / 2 + 255) / 256, 256>>>(src, px, xf);

    dim3 gProj(4, 32);
    dim3 gFfn1(16, 32);
    dim3 gAttn(BB * HH, SS / 128);

    for (int l = 0; l < LAY; l++) {
        size_t ws_proj = (size_t)l * 4 * 8 * TILE_ELEMS;
        size_t ws_w1   = (size_t)l * 16 * 8 * TILE_ELEMS;
        size_t ws_w2   = (size_t)l * 4 * 32 * TILE_ELEMS;

        // QKV: fp16 2-term, split-bf16 bhsk out (Q pre-scaled by 1/8)
        hmma_gemm_h<0,1,false><<<gProj, GT, HSMEM_DYN>>>(xf, wqh + ws_proj, bq + l * HH * DK,
                                                         nullptr, nullptr, qh, ql, NN, DD, DD, 0.125f);
        hmma_gemm_h<0,1,false><<<gProj, GT, HSMEM_DYN>>>(xf, wkh + ws_proj, bk + l * HH * DK,
                                                         nullptr, nullptr, kh, kl, NN, DD, DD, 1.0f);
        hmma_gemm_h<0,1,false><<<gProj, GT, HSMEM_DYN>>>(xf, wvh + ws_proj, bv + l * HH * DK,
                                                         nullptr, nullptr, vh, vl, NN, DD, DD, 1.0f);

        attn_hmma<<<gAttn, 256, ATT_SMEM>>>(qh, ql, kh, kl, vh, vl, of);

        // O-proj: fp16 2-term, bhsk-gather A, fp32 out
        hmma_gemm_h<1,0,false><<<gProj, GT, HSMEM_DYN>>>(of, woh + ws_proj, bo + l * DD,
                                                         pt, nullptr, nullptr, nullptr, NN, DD, DD, 1.0f);
        ln_kernel<true,true><<<NN, 128>>>(pt, ln1g + l * DD, ln1b + l * DD, px, xf, 1e-5f);

        hmma_gemm_h<0,2,true ><<<gFfn1, GT, HSMEM_DYN>>>(xf, w1h + ws_w1, b1 + l * DFF,
                                                         nullptr, ff, nullptr, nullptr, NN, DFF, DD, 1.0f);
        hmma_gemm_h<0,0,false><<<gProj, GT, HSMEM_DYN>>>(ff, w2h + ws_w2, b2 + l * DD,
                                                         pt, nullptr, nullptr, nullptr, NN, DD, DFF, 1.0f);
        ln_kernel<true,true><<<NN, 128>>>(pt, ln2g + l * DD, ln2b + l * DD, px, xf, 1e-5f);
    }

    ln_kernel<false,false><<<NN, 128>>>(px, lnfg, lnfb, out, nullptr, 1e-6f);
}

// round 17
// speedup vs baseline: 1.8992x; 1.4375x over previous
// rev: r17 fp16 attention (QK single, V 2-term) + FFN W-single
#include <cuda_runtime.h>
#include <cuda_fp16.h>
#include <math.h>
#include <stdint.h>

#define LAY 6
#define HH  8
#define DD  512
#define DK  64
#define DFF 2048
#define BB  8
#define SS  1024
#define NN  (BB*SS)

// ---------------- scratch ----------------
__device__ float  g_x[NN*DD];
__device__ float  g_t[NN*DD];
__device__ __half g_xf[NN*DD];        // fp16 x (GEMM A)
__device__ __half g_ff[NN*DFF];       // fp16 ffn hidden
__device__ __half g_of[NN*DD];        // fp16 attention out (bhsk)
__device__ __half g_qf[NN*DD];        // fp16 Q (bhsk, prescaled)
__device__ __half g_kf[NN*DD];        // fp16 K (bhsk)
__device__ __half g_v2[2*NN*DD];      // fp16 V hi/lo (bhsk)

#define TILE_ELEMS 16384
__device__ __half g_wq_h[LAY*4*8*TILE_ELEMS];
__device__ __half g_wk_h[LAY*4*8*TILE_ELEMS];
__device__ __half g_wv_h[LAY*4*8*TILE_ELEMS];
__device__ __half g_wo_h[LAY*4*8*TILE_ELEMS];
__device__ __half g_w1h[LAY*16*8*TILE_ELEMS];
__device__ __half g_w2h[LAY*4*32*TILE_ELEMS];

// ---------------- PTX helpers ----------------
__device__ __forceinline__ uint32_t smem_u32(const void* p) {
    uint32_t a;
    asm("{ .reg .u64 t; cvta.to.shared.u64 t, %1; cvt.u32.u64 %0, t; }" : "=r"(a) : "l"(p));
    return a;
}
#define LDSM4(r, a) \
    asm volatile("ldmatrix.sync.aligned.m8n8.x4.shared.b16 {%0,%1,%2,%3}, [%4];" \
        : "=r"((r)[0]), "=r"((r)[1]), "=r"((r)[2]), "=r"((r)[3]) : "r"(a))
#define LDSM4T(r, a) \
    asm volatile("ldmatrix.sync.aligned.m8n8.x4.trans.shared.b16 {%0,%1,%2,%3}, [%4];" \
        : "=r"((r)[0]), "=r"((r)[1]), "=r"((r)[2]), "=r"((r)[3]) : "r"(a))
#define MMA_F16(d, a, b0, b1) \
    asm volatile("mma.sync.aligned.m16n8k16.row.col.f32.f16.f16.f32 " \
        "{%0,%1,%2,%3}, {%4,%5,%6,%7}, {%8,%9}, {%0,%1,%2,%3};" \
        : "+f"((d)[0]), "+f"((d)[1]), "+f"((d)[2]), "+f"((d)[3]) \
        : "r"((a)[0]), "r"((a)[1]), "r"((a)[2]), "r"((a)[3]), "r"(b0), "r"(b1))
#define CP16(dst, src) \
    asm volatile("cp.async.cg.shared.global [%0], [%1], 16;" :: "r"(dst), "l"(src))
#define CP_COMMIT() asm volatile("cp.async.commit_group;" ::: "memory")
#define CP_WAIT1()  asm volatile("cp.async.wait_group 1;" ::: "memory")

__device__ __forceinline__ float fexp(float x) {
    float t = x * 1.44269504f;
    t = fmaxf(t, -126.0f);
    float i = rintf(t);
    float f = t - i;
    float p =       1.54035304e-4f;
    p = fmaf(p, f, 1.33335581e-3f);
    p = fmaf(p, f, 9.61812910e-3f);
    p = fmaf(p, f, 5.55041086e-2f);
    p = fmaf(p, f, 2.40226507e-1f);
    p = fmaf(p, f, 6.93147182e-1f);
    p = fmaf(p, f, 1.0f);
    return p * __int_as_float(((int)i + 127) << 23);
}

__device__ __forceinline__ void split2h(float a, float b, uint32_t& hi, uint32_t& lo) {
    __half2 h = __floats2half2_rn(a, b);
    __half2 l = __floats2half2_rn(a - __half2float(__low2half(h)),
                                  b - __half2float(__high2half(h)));
    hi = *(uint32_t*)&h;
    lo = *(uint32_t*)&l;
}
__device__ __forceinline__ uint32_t h2pack(float a, float b) {
    __half2 h = __floats2half2_rn(a, b);
    return *(uint32_t*)&h;
}

// ---------------- weight pre-split: fp16 hi/lo tiles ----------------
__device__ __forceinline__ void split_tile_h(const float* __restrict__ W,
                                             __half* __restrict__ out,
                                             int K, int N, int blocked, int tile,
                                             float (*s)[65]) {
    int kt = tile % (K >> 6);
    int rest = tile / (K >> 6);
    int nt = rest % (N >> 7);
    int l = rest / (N >> 7);
    int n0 = nt << 7, k0 = kt << 6;
    int t = threadIdx.x;
#pragma unroll
    for (int r = 0; r < 32; r++) {
        int i = r * 256 + t;
        int k = i >> 7, n = i & 127;
        float x;
        if (blocked) x = W[(((size_t)l * HH + ((n0 + n) >> 6)) * DD + k0 + k) * DK + ((n0 + n) & 63)];
        else         x = W[((size_t)l * K + k0 + k) * N + n0 + n];
        s[n][k] = x;
    }
    __syncthreads();
    uint32_t* oh = (uint32_t*)(out + (size_t)tile * TILE_ELEMS);
    uint32_t* ol = oh + 4096;
#pragma unroll
    for (int r = 0; r < 16; r++) {
        int i = r * 256 + t;
        int n = i >> 5, k = (i & 31) << 1;
        uint32_t hi, lo;
        split2h(s[n][k], s[n][k + 1], hi, lo);
        oh[n * 32 + (k >> 1)] = hi;
        ol[n * 32 + (k >> 1)] = lo;
    }
}

__global__ __launch_bounds__(256)
void split_all_kernel(const float* Wq, const float* Wk, const float* Wv,
                      const float* Wo, const float* W1, const float* W2,
                      __half* oq, __half* ok, __half* ov,
                      __half* oo, __half* o1, __half* o2) {
    __shared__ float s[128][65];
    int b = blockIdx.x;
    if      (b < 192)  split_tile_h(Wq, oq, DD,  DD,  1, b,        s);
    else if (b < 384)  split_tile_h(Wk, ok, DD,  DD,  1, b - 192,  s);
    else if (b < 576)  split_tile_h(Wv, ov, DD,  DD,  1, b - 384,  s);
    else if (b < 768)  split_tile_h(Wo, oo, DD,  DD,  0, b - 576,  s);
    else if (b < 1536) split_tile_h(W1, o1, DD,  DFF, 0, b - 768,  s);
    else               split_tile_h(W2, o2, DFF, DD,  0, b - 1536, s);
}

// ---------------- positional encoding ----------------
__global__ void add_pe_kernel(const float* __restrict__ src, float* __restrict__ x,
                              __half* __restrict__ xf) {
    int gid = blockIdx.x * 256 + threadIdx.x;
    if (gid >= NN * DD / 2) return;
    int idx = gid * 2;
    int d = idx & (DD - 1);
    int s = (idx >> 9) & (SS - 1);
    int i = d >> 1;
    double div = exp((double)(2 * i) * (-9.210340371976184 / (double)DD));
    double ang = (double)s * div;
    float v0 = src[idx]     + (float)sin(ang);
    float v1 = src[idx + 1] + (float)cos(ang);
    x[idx] = v0; x[idx + 1] = v1;
    ((uint32_t*)xf)[gid] = h2pack(v0, v1);
}

// --- fp16 HMMA GEMM (256x128 CTA, 16 warps of 64x32, 3-stage) ----------------
// stage (40960 B): A 256x(64+16)B @0, B_hi @20480, B_lo @30720
#define HS_BHI 20480
#define HS_BLO 10240
#define HS_STG 40960
#define HSMEM_DYN (3*HS_STG)
#define GT 512

// AMODE 0: A rowmajor.  AMODE 1: A bhsk gather.
// BT 2: B hi+lo (2-term).  BT 1: B hi only (1-term).
// OMODE 0: fp32 rowmajor.  OMODE 2: fp16 rowmajor.  OMODE 3: fp16 bhsk.
// OMODE 4: fp16 hi/lo bhsk.
template<int AMODE, int OMODE, int BT, bool RELU>
__global__ __launch_bounds__(GT, 1)
void hmma_gemm_h(const __half* __restrict__ A, const __half* __restrict__ Bt,
                 const float* __restrict__ bias, float* __restrict__ Cf,
                 __half* __restrict__ Ch,
                 __half* __restrict__ Chi, __half* __restrict__ Clo,
                 int M, int N, int K, float scale) {
    extern __shared__ char smbuf[];
    uint32_t sb = smem_u32(smbuf);
    const int t = threadIdx.x, lane = t & 31, wid = t >> 5;
    const int wm = wid & 3, wn = wid >> 2;
    const int bm = blockIdx.y * 256, bn = blockIdx.x * 128;
    const int nk = K >> 5;
    const int ktile_n = K >> 6;

    float acc[4][4][4];
#pragma unroll
    for (int a = 0; a < 4; a++)
#pragma unroll
        for (int b = 0; b < 4; b++)
#pragma unroll
            for (int c = 0; c < 4; c++) acc[a][b][c] = 0.f;

    auto ISSUE = [&](int kt) {
        uint32_t stg = sb + (kt % 3) * HS_STG;
        // A: 1024 chunks (256 rows x 4)
#pragma unroll
        for (int r = 0; r < 2; r++) {
            int i = r * GT + t;
            int row = i >> 2, ch = i & 3;
            const char* src;
            if (AMODE == 0) {
                src = (const char*)A + (((size_t)(bm + row) * K + kt * 32 + ch * 8) << 1);
            } else {
                int kk = kt * 32 + ch * 8;
                int mm = bm + row;
                src = (const char*)A + (((size_t)(((mm >> 10) << 3) + (kk >> 6))) << 17)
                                     + ((mm & 1023) << 7) + ((kk & 63) << 1);
            }
            CP16(stg + row * 80 + ch * 16, src);
        }
        // B: hi (+lo if BT==2)
        const char* tb = (const char*)(Bt + ((size_t)blockIdx.x * ktile_n + (kt >> 1)) * TILE_ELEMS);
        int half = kt & 1;
#pragma unroll
        for (int r = 0; r < BT; r++) {
            int i = r * GT + t;
            int comp = i >> 9, j = i & 511;
            int row = j >> 2, ch = j & 3;
            CP16(stg + HS_BHI + comp * HS_BLO + row * 80 + ch * 16,
                 tb + comp * 16384 + row * 128 + half * 64 + ch * 16);
        }
    };

    auto COMPUTE = [&](int buf) {
        uint32_t stg = sb + buf * HS_STG;
#pragma unroll
        for (int kk = 0; kk < 2; kk++) {
            int acol = (kk * 16 + (lane >> 4) * 8) * 2;
            uint32_t af[4][4];
#pragma unroll
            for (int mt = 0; mt < 4; mt++) {
                LDSM4(af[mt], stg + (wm * 64 + mt * 16 + (lane & 15)) * 80 + acol);
            }
#pragma unroll
            for (int nt2 = 0; nt2 < 2; nt2++) {
                uint32_t baddr = stg + HS_BHI + (wn * 32 + nt2 * 16 + (lane & 15)) * 80 + acol;
                uint32_t bh[4], bl[4];
                LDSM4(bh, baddr);
                if (BT == 2) LDSM4(bl, baddr + HS_BLO);
#pragma unroll
                for (int mt = 0; mt < 4; mt++) {
                    MMA_F16(acc[mt][nt2 * 2],     af[mt], bh[0], bh[2]);
                    MMA_F16(acc[mt][nt2 * 2 + 1], af[mt], bh[1], bh[3]);
                    if (BT == 2) {
                        MMA_F16(acc[mt][nt2 * 2],     af[mt], bl[0], bl[2]);
                        MMA_F16(acc[mt][nt2 * 2 + 1], af[mt], bl[1], bl[3]);
                    }
                }
            }
        }
    };

    ISSUE(0); CP_COMMIT();
    ISSUE(1); CP_COMMIT();
    for (int kt = 0; kt < nk; kt++) {
        CP_WAIT1();
        __syncthreads();
        if (kt + 2 < nk) ISSUE(kt + 2);
        CP_COMMIT();
        COMPUTE(kt % 3);
    }

    const int mrow = lane >> 2, ncol = (lane & 3) * 2;
#pragma unroll
    for (int mt = 0; mt < 4; mt++) {
#pragma unroll
        for (int nb = 0; nb < 4; nb++) {
            int c = bn + wn * 32 + nb * 8 + ncol;
            float2 bi = *(const float2*)(bias + c);
#pragma unroll
            for (int h = 0; h < 2; h++) {
                int m = bm + wm * 64 + mt * 16 + mrow + h * 8;
                float2 v;
                v.x = (acc[mt][nb][h * 2 + 0] + bi.x) * scale;
                v.y = (acc[mt][nb][h * 2 + 1] + bi.y) * scale;
                if (RELU) { v.x = fmaxf(v.x, 0.f); v.y = fmaxf(v.y, 0.f); }
                if (OMODE == 0) {
                    *(float2*)(Cf + (size_t)m * N + c) = v;
                } else if (OMODE == 2) {
                    ((uint32_t*)Ch)[((size_t)m * N + c) >> 1] = h2pack(v.x, v.y);
                } else {
                    size_t idx = (((size_t)(((m >> 10) << 3) + (c >> 6))) << 16)
                               + ((m & 1023) << 6) + (c & 63);
                    if (OMODE == 3) {
                        ((uint32_t*)Ch)[idx >> 1] = h2pack(v.x, v.y);
                    } else {
                        uint32_t hi, lo;
                        split2h(v.x, v.y, hi, lo);
                        ((uint32_t*)Chi)[idx >> 1] = hi;
                        ((uint32_t*)Clo)[idx >> 1] = lo;
                    }
                }
            }
        }
    }
}

// ---------------- fp16 flash attention (QK single, P single, V 2-term) ------
// smem: Q 128x144B @0; per KV stage (27648): K @0, Vhi @9216, Vlo @18432
#define KVB    18432
#define KV_STG 27648
#define KV_VH  9216
#define ATT_SMEM (18432 + 3*27648)

__global__ __launch_bounds__(256)
void attn_hmma(const __half* __restrict__ Qf, const __half* __restrict__ Kf,
               const __half* __restrict__ Vh, const __half* __restrict__ Vl,
               __half* __restrict__ Of) {
    extern __shared__ char smbuf[];
    uint32_t sb = smem_u32(smbuf);
    const int t = threadIdx.x, lane = t & 31, w = t >> 5;
    const int bh = blockIdx.x;
    const int qbase = blockIdx.y * 128;

    auto ISSUEKV = [&](int c) {
        uint32_t stg = sb + KVB + (c % 3) * KV_STG;
        int kc = c * 64;
#pragma unroll
        for (int r = 0; r < 6; r++) {
            int i = r * 256 + t;            // 1536 chunks: K 512, Vh 512, Vl 512
            int seg = i >> 9;
            int j = i & 511;
            int row = j >> 3, ch = j & 7;
            const char* base = (seg == 0) ? (const char*)Kf
                             : (seg == 1) ? (const char*)Vh : (const char*)Vl;
            const char* src = base + (((size_t)(bh * SS + kc + row) * DK + ch * 8) << 1);
            CP16(stg + seg * 9216 + row * 144 + ch * 16, src);
        }
    };

    ISSUEKV(0); CP_COMMIT();
    ISSUEKV(1); CP_COMMIT();

    // stage Q (single fp16, prescaled)
#pragma unroll
    for (int r = 0; r < 4; r++) {
        int i = r * 256 + t;
        int row = i >> 3, ch = i & 7;
        const char* src = (const char*)Qf + (((size_t)(bh * SS + qbase + row) * DK + ch * 8) << 1);
        *(uint4*)(smbuf + row * 144 + ch * 16) = *(const uint4*)src;
    }
    __syncthreads();

    uint32_t qf[4][4];
#pragma unroll
    for (int kb = 0; kb < 4; kb++) {
        LDSM4(qf[kb], sb + (w * 16 + (lane & 15)) * 144 + (kb * 16 + (lane >> 4) * 8) * 2);
    }

    float o[8][4];
#pragma unroll
    for (int i = 0; i < 8; i++)
#pragma unroll
        for (int j = 0; j < 4; j++) o[i][j] = 0.f;
    float m0 = -1.0e30f, m1 = -1.0e30f, l0 = 0.f, l1 = 0.f;

    for (int c = 0; c < SS / 64; c++) {
        CP_WAIT1();
        __syncthreads();
        if (c + 2 < SS / 64) ISSUEKV(c + 2);
        CP_COMMIT();
        uint32_t stg = sb + KVB + (c % 3) * KV_STG;

        // S = Q K^T (single fp16)
        float s[8][4];
#pragma unroll
        for (int i = 0; i < 8; i++)
#pragma unroll
            for (int j = 0; j < 4; j++) s[i][j] = 0.f;
#pragma unroll
        for (int kvb = 0; kvb < 4; kvb++) {
#pragma unroll
            for (int kb = 0; kb < 4; kb++) {
                uint32_t addr = stg + (kvb * 16 + (lane & 15)) * 144 + (kb * 16 + (lane >> 4) * 8) * 2;
                uint32_t kfr[4];
                LDSM4(kfr, addr);
                MMA_F16(s[kvb * 2],     qf[kb], kfr[0], kfr[2]);
                MMA_F16(s[kvb * 2 + 1], qf[kb], kfr[1], kfr[3]);
            }
        }

        // online softmax
        float cm0 = -1.0e30f, cm1 = -1.0e30f;
#pragma unroll
        for (int nb = 0; nb < 8; nb++) {
            cm0 = fmaxf(cm0, fmaxf(s[nb][0], s[nb][1]));
            cm1 = fmaxf(cm1, fmaxf(s[nb][2], s[nb][3]));
        }
        cm0 = fmaxf(cm0, __shfl_xor_sync(0xffffffffu, cm0, 1));
        cm0 = fmaxf(cm0, __shfl_xor_sync(0xffffffffu, cm0, 2));
        cm1 = fmaxf(cm1, __shfl_xor_sync(0xffffffffu, cm1, 1));
        cm1 = fmaxf(cm1, __shfl_xor_sync(0xffffffffu, cm1, 2));
        float m0n = fmaxf(m0, cm0), m1n = fmaxf(m1, cm1);
        float c0 = fexp(m0 - m0n), c1 = fexp(m1 - m1n);
#pragma unroll
        for (int nb = 0; nb < 8; nb++) {
            o[nb][0] *= c0; o[nb][1] *= c0;
            o[nb][2] *= c1; o[nb][3] *= c1;
        }
        float ls0 = 0.f, ls1 = 0.f;
#pragma unroll
        for (int nb = 0; nb < 8; nb++) {
            s[nb][0] = fexp(s[nb][0] - m0n);
            s[nb][1] = fexp(s[nb][1] - m0n);
            s[nb][2] = fexp(s[nb][2] - m1n);
            s[nb][3] = fexp(s[nb][3] - m1n);
            ls0 += s[nb][0] + s[nb][1];
            ls1 += s[nb][2] + s[nb][3];
        }
        ls0 += __shfl_xor_sync(0xffffffffu, ls0, 1);
        ls0 += __shfl_xor_sync(0xffffffffu, ls0, 2);
        ls1 += __shfl_xor_sync(0xffffffffu, ls1, 1);
        ls1 += __shfl_xor_sync(0xffffffffu, ls1, 2);
        l0 = l0 * c0 + ls0;
        l1 = l1 * c1 + ls1;
        m0 = m0n; m1 = m1n;

        // O += P V  (P single fp16, V hi/lo 2-term)
#pragma unroll
        for (int kb = 0; kb < 4; kb++) {
            uint32_t ph[4];
            ph[0] = h2pack(s[2 * kb][0],     s[2 * kb][1]);
            ph[1] = h2pack(s[2 * kb][2],     s[2 * kb][3]);
            ph[2] = h2pack(s[2 * kb + 1][0], s[2 * kb + 1][1]);
            ph[3] = h2pack(s[2 * kb + 1][2], s[2 * kb + 1][3]);
#pragma unroll
            for (int db = 0; db < 4; db++) {
                uint32_t addr = stg + KV_VH + (kb * 16 + (lane & 15)) * 144 + (db * 16 + (lane >> 4) * 8) * 2;
                uint32_t vfh[4], vfl[4];
                LDSM4T(vfh, addr);
                LDSM4T(vfl, addr + 9216);
                MMA_F16(o[db * 2],     ph, vfh[0], vfh[1]);
                MMA_F16(o[db * 2],     ph, vfl[0], vfl[1]);
                MMA_F16(o[db * 2 + 1], ph, vfh[2], vfh[3]);
                MMA_F16(o[db * 2 + 1], ph, vfl[2], vfl[3]);
            }
        }
    }

    float inv0 = 1.f / l0, inv1 = 1.f / l1;
    int r0 = qbase + w * 16 + (lane >> 2);
    int c0c = (lane & 3) * 2;
#pragma unroll
    for (int db = 0; db < 8; db++) {
        int c = db * 8 + c0c;
        size_t idx0 = ((size_t)bh * SS + r0) * DK + c;
        ((uint32_t*)Of)[idx0 >> 1] = h2pack(o[db][0] * inv0, o[db][1] * inv0);
        size_t idx1 = ((size_t)bh * SS + r0 + 8) * DK + c;
        ((uint32_t*)Of)[idx1 >> 1] = h2pack(o[db][2] * inv1, o[db][3] * inv1);
    }
}

// ---------------- LayerNorm ----------------
template<bool ADD, bool SPLIT>
__global__ __launch_bounds__(128)
void ln_kernel(const float* __restrict__ src, const float* __restrict__ gamma,
               const float* __restrict__ beta, float* __restrict__ xio,
               __half* __restrict__ xf, float eps) {
    int row = blockIdx.x;
    int t = threadIdx.x;
    int lane = t & 31, wid = t >> 5;
    const float4* sp = (const float4*)(src + (size_t)row * DD);
    float4 v = sp[t];

    __shared__ float red[4];
    __shared__ float bsum, bvar;

    float s = (v.x + v.y) + (v.z + v.w);
#pragma unroll
    for (int o = 16; o > 0; o >>= 1) s += __shfl_xor_sync(0xffffffffu, s, o);
    if (lane == 0) red[wid] = s;
    __syncthreads();
    if (t == 0) bsum = (red[0] + red[1]) + (red[2] + red[3]);
    __syncthreads();
    float mu = bsum * (1.f / DD);

    float dx = v.x - mu, dy = v.y - mu, dz = v.z - mu, dw = v.w - mu;
    float s2 = (dx * dx + dy * dy) + (dz * dz + dw * dw);
#pragma unroll
    for (int o = 16; o > 0; o >>= 1) s2 += __shfl_xor_sync(0xffffffffu, s2, o);
    if (lane == 0) red[wid] = s2;
    __syncthreads();
    if (t == 0) bvar = (red[0] + red[1]) + (red[2] + red[3]);
    __syncthreads();
    float rstd = rsqrtf(bvar * (1.f / DD) + eps);

    int c = t * 4;
    float4 g = *(const float4*)(gamma + c);
    float4 b = *(const float4*)(beta + c);
    float4 o4;
    o4.x = dx * rstd * g.x + b.x;
    o4.y = dy * rstd * g.y + b.y;
    o4.z = dz * rstd * g.z + b.z;
    o4.w = dw * rstd * g.w + b.w;
    float4* xp = (float4*)(xio + (size_t)row * DD);
    if (ADD) {
        float4 xo = xp[t];
        o4.x += xo.x; o4.y += xo.y; o4.z += xo.z; o4.w += xo.w;
    }
    xp[t] = o4;
    if (SPLIT) {
        size_t pidx = ((size_t)row * DD + c) >> 1;
        ((uint32_t*)xf)[pidx]     = h2pack(o4.x, o4.y);
        ((uint32_t*)xf)[pidx + 1] = h2pack(o4.z, o4.w);
    }
}

// ---------------- driver ----------------
extern "C" void kernel_launch(void* const* d_in, const int* in_sizes, int n_in,
                              void* d_out, int out_size) {
    const float* src  = (const float*)d_in[0];
    const float* Wq   = (const float*)d_in[1];
    const float* bq   = (const float*)d_in[2];
    const float* Wk   = (const float*)d_in[3];
    const float* bk   = (const float*)d_in[4];
    const float* Wv   = (const float*)d_in[5];
    const float* bv   = (const float*)d_in[6];
    const float* Wo   = (const float*)d_in[7];
    const float* bo   = (const float*)d_in[8];
    const float* ln1g = (const float*)d_in[9];
    const float* ln1b = (const float*)d_in[10];
    const float* W1   = (const float*)d_in[11];
    const float* b1   = (const float*)d_in[12];
    const float* W2   = (const float*)d_in[13];
    const float* b2   = (const float*)d_in[14];
    const float* ln2g = (const float*)d_in[15];
    const float* ln2b = (const float*)d_in[16];
    const float* lnfg = (const float*)d_in[17];
    const float* lnfb = (const float*)d_in[18];
    float* out = (float*)d_out;

    float *px, *pt;
    __half *xf, *ff, *of, *qf, *kf, *v2, *wqh, *wkh, *wvh, *woh, *w1h, *w2h;
    cudaGetSymbolAddress((void**)&px, g_x);
    cudaGetSymbolAddress((void**)&pt, g_t);
    cudaGetSymbolAddress((void**)&xf, g_xf);
    cudaGetSymbolAddress((void**)&ff, g_ff);
    cudaGetSymbolAddress((void**)&of, g_of);
    cudaGetSymbolAddress((void**)&qf, g_qf);
    cudaGetSymbolAddress((void**)&kf, g_kf);
    cudaGetSymbolAddress((void**)&v2, g_v2);
    cudaGetSymbolAddress((void**)&wqh, g_wq_h);
    cudaGetSymbolAddress((void**)&wkh, g_wk_h);
    cudaGetSymbolAddress((void**)&wvh, g_wv_h);
    cudaGetSymbolAddress((void**)&woh, g_wo_h);
    cudaGetSymbolAddress((void**)&w1h, g_w1h);
    cudaGetSymbolAddress((void**)&w2h, g_w2h);

    __half *vh = v2, *vl = v2 + (size_t)NN * DD;

    cudaFuncSetAttribute(hmma_gemm_h<0,3,2,false>, cudaFuncAttributeMaxDynamicSharedMemorySize, HSMEM_DYN);
    cudaFuncSetAttribute(hmma_gemm_h<0,4,2,false>, cudaFuncAttributeMaxDynamicSharedMemorySize, HSMEM_DYN);
    cudaFuncSetAttribute(hmma_gemm_h<1,0,2,false>, cudaFuncAttributeMaxDynamicSharedMemorySize, HSMEM_DYN);
    cudaFuncSetAttribute(hmma_gemm_h<0,2,1,true >, cudaFuncAttributeMaxDynamicSharedMemorySize, HSMEM_DYN);
    cudaFuncSetAttribute(hmma_gemm_h<0,0,1,false>, cudaFuncAttributeMaxDynamicSharedMemorySize, HSMEM_DYN);
    cudaFuncSetAttribute(attn_hmma, cudaFuncAttributeMaxDynamicSharedMemorySize, ATT_SMEM);

    split_all_kernel<<<2304, 256>>>(Wq, Wk, Wv, Wo, W1, W2, wqh, wkh, wvh, woh, w1h, w2h);
    add_pe_kernel<<<(NN * DD / 2 + 255) / 256, 256>>>(src, px, xf);

    dim3 gProj(4, 32);
    dim3 gFfn1(16, 32);
    dim3 gAttn(BB * HH, SS / 128);

    for (int l = 0; l < LAY; l++) {
        size_t ws_proj = (size_t)l * 4 * 8 * TILE_ELEMS;
        size_t ws_w1   = (size_t)l * 16 * 8 * TILE_ELEMS;
        size_t ws_w2   = (size_t)l * 4 * 32 * TILE_ELEMS;

        // Q,K: fp16 single bhsk out (Q pre-scaled); V: fp16 hi/lo bhsk out
        hmma_gemm_h<0,3,2,false><<<gProj, GT, HSMEM_DYN>>>(xf, wqh + ws_proj, bq + l * HH * DK,
                                                           nullptr, qf, nullptr, nullptr, NN, DD, DD, 0.125f);
        hmma_gemm_h<0,3,2,false><<<gProj, GT, HSMEM_DYN>>>(xf, wkh + ws_proj, bk + l * HH * DK,
                                                           nullptr, kf, nullptr, nullptr, NN, DD, DD, 1.0f);
        hmma_gemm_h<0,4,2,false><<<gProj, GT, HSMEM_DYN>>>(xf, wvh + ws_proj, bv + l * HH * DK,
                                                           nullptr, nullptr, vh, vl, NN, DD, DD, 1.0f);

        attn_hmma<<<gAttn, 256, ATT_SMEM>>>(qf, kf, vh, vl, of);

        hmma_gemm_h<1,0,2,false><<<gProj, GT, HSMEM_DYN>>>(of, woh + ws_proj, bo + l * DD,
                                                           pt, nullptr, nullptr, nullptr, NN, DD, DD, 1.0f);
        ln_kernel<true,true><<<NN, 128>>>(pt, ln1g + l * DD, ln1b + l * DD, px, xf, 1e-5f);

        // FFN: B single-term
        hmma_gemm_h<0,2,1,true ><<<gFfn1, GT, HSMEM_DYN>>>(xf, w1h + ws_w1, b1 + l * DFF,
                                                           nullptr, ff, nullptr, nullptr, NN, DFF, DD, 1.0f);
        hmma_gemm_h<0,0,1,false><<<gProj, GT, HSMEM_DYN>>>(ff, w2h + ws_w2, b2 + l * DD,
                                                           pt, nullptr, nullptr, nullptr, NN, DD, DFF, 1.0f);
        ln_kernel<true,true><<<NN, 128>>>(pt, ln2g + l * DD, ln2b + l * DD, px, xf, 1e-5f);
    }

    ln_kernel<false,false><<<NN, 128>>>(px, lnfg, lnfb, out, nullptr, 1e-6f);
}